// round 1
// baseline (speedup 1.0000x reference)
#include <cuda_runtime.h>
#include <math.h>
#include <stdint.h>

// Problem constants
#define NB 16
#define NA 1024
#define NT 512
#define ND 256
#define TWO_D 512

// ---------------- scratch (no allocations allowed) ----------------
__device__ float g_art[2][NB * NA * ND];   // 2 x 16 MB
__device__ float g_tpl[2][NB * NT * ND];   // 2 x 8 MB
__device__ float g_a2[NB * NA];
__device__ float g_t2[NB * NT];
__device__ float g_rowmax[NB * NA];

// ---------------- embedding gather ----------------
__global__ void gather_kernel(const int* __restrict__ words,
                              const float* __restrict__ emb,
                              float* __restrict__ out, int nrows) {
    int idx = blockIdx.x * blockDim.x + threadIdx.x;  // float4 index
    int total = nrows * (ND / 4);
    if (idx >= total) return;
    int row = idx >> 6;   // / (ND/4)
    int d4  = idx & 63;
    int w = words[row];
    reinterpret_cast<float4*>(out)[(size_t)row * 64 + d4] =
        reinterpret_cast<const float4*>(emb)[(size_t)w * 64 + d4];
}

// ---------------- fused dilated-conv GLU residual block ----------------
// y = conv1d(x, W[k,d,c], dil, 'same') + bias ; a,g = split(y) ; out = x + a*sigmoid(g)
// GEMM view: M = B*L rows, N = 512 (handled as 256 a/g pairs), K = 3*256.
#define BM 128
#define BPAIR 32      // 32 pairs => 64 real output channels per block
#define BK 32
#define AS_STRIDE 132 // padded (mult of 4, varies bank with d)
#define BS_STRIDE 36

__global__ __launch_bounds__(256, 2)
void resblock_kernel(const float* __restrict__ X, float* __restrict__ Y,
                     const float* __restrict__ W, const float* __restrict__ bias,
                     int L, int dil) {
    __shared__ float As[BK * AS_STRIDE];
    __shared__ float Bsa[BK * BS_STRIDE];
    __shared__ float Bsg[BK * BS_STRIDE];

    const int tid = threadIdx.x;
    const int rowBase = blockIdx.x * BM;   // global row (b,l) flattened
    const int cBase = blockIdx.y * BPAIR;  // pair/channel base (< 256)

    // block never straddles a batch: L in {1024,512}, BM=128 divides both
    const int bb = rowBase / L;
    const int lBase = rowBase - bb * L;

    const int rg = tid >> 4;     // 0..15, 8 rows each
    const int pg = tid & 15;     // 0..15, 2 pairs each
    const int r0 = rg * 8;
    const int p0 = pg * 2;

    float acc_a[8][2], acc_g[8][2];
#pragma unroll
    for (int i = 0; i < 8; i++) {
        acc_a[i][0] = acc_a[i][1] = 0.f;
        acc_g[i][0] = acc_g[i][1] = 0.f;
    }

    for (int k = 0; k < 3; k++) {
        const int shift = (k - 1) * dil;
        const float* Wk = W + (size_t)k * ND * TWO_D;
        for (int dBase = 0; dBase < ND; dBase += BK) {
            __syncthreads();
            // ---- load A tile (transposed into As[d][m]) : 128 rows x 32 d ----
#pragma unroll
            for (int q = 0; q < 4; q++) {
                int f4id = tid + q * 256;       // 0..1023
                int m = f4id >> 3;              // 0..127
                int dq = (f4id & 7) * 4;        // 0..28
                int ls = lBase + m + shift;
                float4 v = make_float4(0.f, 0.f, 0.f, 0.f);
                if (ls >= 0 && ls < L) {
                    v = *reinterpret_cast<const float4*>(
                        X + ((size_t)(bb * L + ls)) * ND + dBase + dq);
                }
                As[(dq + 0) * AS_STRIDE + m] = v.x;
                As[(dq + 1) * AS_STRIDE + m] = v.y;
                As[(dq + 2) * AS_STRIDE + m] = v.z;
                As[(dq + 3) * AS_STRIDE + m] = v.w;
            }
            // ---- load B tiles (a cols and g cols) : 32 d x 32 p each ----
            {
                int d = tid >> 3;               // 0..31
                int p = (tid & 7) * 4;          // 0..28
                const float* wrow = Wk + (size_t)(dBase + d) * TWO_D;
                float4 va = *reinterpret_cast<const float4*>(wrow + cBase + p);
                float4 vg = *reinterpret_cast<const float4*>(wrow + 256 + cBase + p);
                *reinterpret_cast<float4*>(&Bsa[d * BS_STRIDE + p]) = va;
                *reinterpret_cast<float4*>(&Bsg[d * BS_STRIDE + p]) = vg;
            }
            __syncthreads();
            // ---- inner product ----
#pragma unroll
            for (int dd = 0; dd < BK; dd++) {
                float4 ra0 = *reinterpret_cast<const float4*>(&As[dd * AS_STRIDE + r0]);
                float4 ra1 = *reinterpret_cast<const float4*>(&As[dd * AS_STRIDE + r0 + 4]);
                float2 fa = *reinterpret_cast<const float2*>(&Bsa[dd * BS_STRIDE + p0]);
                float2 fg = *reinterpret_cast<const float2*>(&Bsg[dd * BS_STRIDE + p0]);
                float ar[8] = {ra0.x, ra0.y, ra0.z, ra0.w, ra1.x, ra1.y, ra1.z, ra1.w};
#pragma unroll
                for (int i = 0; i < 8; i++) {
                    acc_a[i][0] = fmaf(ar[i], fa.x, acc_a[i][0]);
                    acc_a[i][1] = fmaf(ar[i], fa.y, acc_a[i][1]);
                    acc_g[i][0] = fmaf(ar[i], fg.x, acc_g[i][0]);
                    acc_g[i][1] = fmaf(ar[i], fg.y, acc_g[i][1]);
                }
            }
        }
    }

    // ---- epilogue: GLU + residual ----
#pragma unroll
    for (int i = 0; i < 8; i++) {
        size_t gr = (size_t)(rowBase + r0 + i);
#pragma unroll
        for (int j = 0; j < 2; j++) {
            int c = cBase + p0 + j;
            float a = acc_a[i][j] + bias[c];
            float g = acc_g[i][j] + bias[256 + c];
            float sg = 1.f / (1.f + expf(-g));
            Y[gr * ND + c] = X[gr * ND + c] + a * sg;
        }
    }
}

// ---------------- squared norms per row ----------------
__global__ void norm_kernel(const float* __restrict__ X, float* __restrict__ out) {
    int row = blockIdx.x;
    int tid = threadIdx.x;  // 64 threads, one float4 each
    float4 v = reinterpret_cast<const float4*>(X + (size_t)row * ND)[tid];
    float s = v.x * v.x + v.y * v.y + v.z * v.z + v.w * v.w;
#pragma unroll
    for (int off = 16; off > 0; off >>= 1)
        s += __shfl_down_sync(0xFFFFFFFFu, s, off);
    __shared__ float ws[2];
    if ((tid & 31) == 0) ws[tid >> 5] = s;
    __syncthreads();
    if (tid == 0) out[row] = ws[0] + ws[1];
}

// ---------------- distance + row-max ----------------
// For each batch b, article tile of 64 rows: rowmax_a = max_t exp(-max(||a-t||^2,0)) * masks
#define DA 64
#define DT 64
#define DS_STRIDE 68

__global__ __launch_bounds__(256)
void dist_kernel(const float* __restrict__ art, const float* __restrict__ tpl,
                 const float* __restrict__ a2, const float* __restrict__ t2,
                 const float* __restrict__ am, const float* __restrict__ tm,
                 float* __restrict__ rowmax_out) {
    const int b = blockIdx.y;
    const int aBase = blockIdx.x * DA;  // within batch
    __shared__ float As[32 * DS_STRIDE];
    __shared__ float Ts[32 * DS_STRIDE];
    __shared__ int rmax[DA];

    const int tid = threadIdx.x;
    if (tid < DA) rmax[tid] = 0;  // exp(-d) >= 0 so int-bits compare works

    const int ag = tid >> 4, tg = tid & 15;
    const int ar0 = ag * 4, tc0 = tg * 4;

    float thmax[4] = {0.f, 0.f, 0.f, 0.f};

    float a2v[4], amv[4];
#pragma unroll
    for (int i = 0; i < 4; i++) {
        a2v[i] = a2[b * NA + aBase + ar0 + i];
        amv[i] = am[b * NA + aBase + ar0 + i];
    }

    for (int tTile = 0; tTile < NT / DT; tTile++) {
        float acc[4][4];
#pragma unroll
        for (int i = 0; i < 4; i++)
#pragma unroll
            for (int j = 0; j < 4; j++) acc[i][j] = 0.f;

        for (int dBase = 0; dBase < ND; dBase += 32) {
            __syncthreads();
#pragma unroll
            for (int q = 0; q < 2; q++) {
                int f4id = tid + q * 256;   // 0..511
                int m = f4id >> 3;          // 0..63
                int dq = (f4id & 7) * 4;
                float4 va = *reinterpret_cast<const float4*>(
                    art + ((size_t)(b * NA + aBase + m)) * ND + dBase + dq);
                float4 vt = *reinterpret_cast<const float4*>(
                    tpl + ((size_t)(b * NT + tTile * DT + m)) * ND + dBase + dq);
                As[(dq + 0) * DS_STRIDE + m] = va.x;
                As[(dq + 1) * DS_STRIDE + m] = va.y;
                As[(dq + 2) * DS_STRIDE + m] = va.z;
                As[(dq + 3) * DS_STRIDE + m] = va.w;
                Ts[(dq + 0) * DS_STRIDE + m] = vt.x;
                Ts[(dq + 1) * DS_STRIDE + m] = vt.y;
                Ts[(dq + 2) * DS_STRIDE + m] = vt.z;
                Ts[(dq + 3) * DS_STRIDE + m] = vt.w;
            }
            __syncthreads();
#pragma unroll
            for (int dd = 0; dd < 32; dd++) {
                float4 ra = *reinterpret_cast<const float4*>(&As[dd * DS_STRIDE + ar0]);
                float4 rt = *reinterpret_cast<const float4*>(&Ts[dd * DS_STRIDE + tc0]);
                float av[4] = {ra.x, ra.y, ra.z, ra.w};
                float tv[4] = {rt.x, rt.y, rt.z, rt.w};
#pragma unroll
                for (int i = 0; i < 4; i++)
#pragma unroll
                    for (int j = 0; j < 4; j++)
                        acc[i][j] = fmaf(av[i], tv[j], acc[i][j]);
            }
        }
        // epilogue for this t tile
#pragma unroll
        for (int j = 0; j < 4; j++) {
            int t = tTile * DT + tc0 + j;
            float t2v = t2[b * NT + t];
            float tmv = tm[b * NT + t];
#pragma unroll
            for (int i = 0; i < 4; i++) {
                float dist = a2v[i] + t2v - 2.f * acc[i][j];
                dist = fmaxf(dist, 0.f);
                float s = expf(-dist) * amv[i] * tmv;
                thmax[i] = fmaxf(thmax[i], s);
            }
        }
    }
#pragma unroll
    for (int i = 0; i < 4; i++)
        atomicMax(&rmax[ar0 + i], __float_as_int(thmax[i]));
    __syncthreads();
    if (tid < DA)
        rowmax_out[b * NA + aBase + tid] = __int_as_float(rmax[tid]);
}

// ---------------- top-10 + MLP ----------------
__global__ void topk_mlp_kernel(const float* __restrict__ rowmax,
                                const float* __restrict__ ff1w,
                                const float* __restrict__ ff1b,
                                const float* __restrict__ ff2w,
                                const float* __restrict__ ff2b,
                                float* __restrict__ out) {
    int b = blockIdx.x;
    __shared__ float vals[NA];
    __shared__ float sv[256];
    __shared__ int si[256];
    __shared__ float top[10];
    int tid = threadIdx.x;
#pragma unroll
    for (int q = 0; q < 4; q++) vals[tid + q * 256] = rowmax[b * NA + tid + q * 256];
    __syncthreads();
    for (int it = 0; it < 10; it++) {
        float best = -1.f;
        int bi = 0;
        for (int i = tid; i < NA; i += 256) {
            if (vals[i] > best) { best = vals[i]; bi = i; }
        }
        sv[tid] = best;
        si[tid] = bi;
        __syncthreads();
        for (int off = 128; off > 0; off >>= 1) {
            if (tid < off) {
                if (sv[tid + off] > sv[tid]) { sv[tid] = sv[tid + off]; si[tid] = si[tid + off]; }
            }
            __syncthreads();
        }
        if (tid == 0) { top[it] = sv[0]; vals[si[0]] = -1.f; }
        __syncthreads();
    }
    if (tid == 0) {
        float o = ff2b[0];
        for (int j = 0; j < 10; j++) {
            float h = ff1b[j];
            for (int i = 0; i < 10; i++) h += top[i] * ff1w[i * 10 + j];
            h = fmaxf(h, 0.f);
            o += h * ff2w[j];
        }
        out[b] = o;
    }
}

// ---------------- launcher ----------------
extern "C" void kernel_launch(void* const* d_in, const int* in_sizes, int n_in,
                              void* d_out, int out_size) {
    const int* art_w   = (const int*)d_in[0];
    // d_in[1]  article_char  (unused)
    const int* tpl_w   = (const int*)d_in[2];
    // d_in[3]  template_char (unused)
    const float* am    = (const float*)d_in[4];
    const float* tm    = (const float*)d_in[5];
    const float* emb   = (const float*)d_in[6];
    const float* exp_w = (const float*)d_in[7];
    const float* exp_b = (const float*)d_in[8];
    const float* ref_w = (const float*)d_in[9];
    const float* ref_b = (const float*)d_in[10];
    const float* ff1w  = (const float*)d_in[11];
    const float* ff1b  = (const float*)d_in[12];
    const float* ff2w  = (const float*)d_in[13];
    const float* ff2b  = (const float*)d_in[14];

    float* artbuf;
    float* tplbuf;
    float* a2p;
    float* t2p;
    float* rmp;
    cudaGetSymbolAddress((void**)&artbuf, g_art);
    cudaGetSymbolAddress((void**)&tplbuf, g_tpl);
    cudaGetSymbolAddress((void**)&a2p, g_a2);
    cudaGetSymbolAddress((void**)&t2p, g_t2);
    cudaGetSymbolAddress((void**)&rmp, g_rowmax);

    float* abuf[2] = {artbuf, artbuf + (size_t)NB * NA * ND};
    float* tbuf[2] = {tplbuf, tplbuf + (size_t)NB * NT * ND};

    gather_kernel<<<(NB * NA * (ND / 4) + 255) / 256, 256>>>(art_w, emb, abuf[0], NB * NA);
    gather_kernel<<<(NB * NT * (ND / 4) + 255) / 256, 256>>>(tpl_w, emb, tbuf[0], NB * NT);

    const int dils[10] = {1, 2, 4, 8, 16, 32, 32, 1, 1, 1};
    int cur = 0;
    for (int i = 0; i < 10; i++) {
        const float* w = (i < 7) ? exp_w + (size_t)i * 3 * ND * TWO_D
                                 : ref_w + (size_t)(i - 7) * 3 * ND * TWO_D;
        const float* bias = (i < 7) ? exp_b + (size_t)i * TWO_D
                                    : ref_b + (size_t)(i - 7) * TWO_D;
        resblock_kernel<<<dim3((NB * NA) / BM, 256 / BPAIR), 256>>>(
            abuf[cur], abuf[1 - cur], w, bias, NA, dils[i]);
        resblock_kernel<<<dim3((NB * NT) / BM, 256 / BPAIR), 256>>>(
            tbuf[cur], tbuf[1 - cur], w, bias, NT, dils[i]);
        cur ^= 1;
    }
    // 10 flips -> cur == 0, final tensors in abuf[0]/tbuf[0]

    norm_kernel<<<NB * NA, 64>>>(abuf[cur], a2p);
    norm_kernel<<<NB * NT, 64>>>(tbuf[cur], t2p);

    dist_kernel<<<dim3(NA / DA, NB), 256>>>(abuf[cur], tbuf[cur], a2p, t2p, am, tm, rmp);

    topk_mlp_kernel<<<NB, 256>>>(rmp, ff1w, ff1b, ff2w, ff2b, (float*)d_out);
}

// round 3
// speedup vs baseline: 1.8633x; 1.8633x over previous
#include <cuda_runtime.h>
#include <cuda_bf16.h>
#include <math.h>
#include <stdint.h>

// Problem constants
#define NB 16
#define NA 1024
#define NT 512
#define ND 256
#define TWO_D 512

// ---------------- scratch (no allocations allowed) ----------------
__device__ float g_art[2][NB * NA * ND];
__device__ float g_tpl[2][NB * NT * ND];
__device__ __nv_bfloat16 g_art_h[2][NB * NA * ND];
__device__ __nv_bfloat16 g_art_m[2][NB * NA * ND];
__device__ __nv_bfloat16 g_tpl_h[2][NB * NT * ND];
__device__ __nv_bfloat16 g_tpl_m[2][NB * NT * ND];
__device__ __nv_bfloat16 g_wth[10 * 3 * TWO_D * ND];
__device__ __nv_bfloat16 g_wtm[10 * 3 * TWO_D * ND];
__device__ float g_a2[NB * NA];
__device__ float g_t2[NB * NT];
__device__ float g_rowmax[NB * NA];

// ---------------- helpers ----------------
__device__ __forceinline__ uint32_t smem_u32(const void* p) {
    uint32_t a;
    asm("{ .reg .u64 t; cvta.to.shared.u64 t, %1; cvt.u32.u64 %0, t; }" : "=r"(a) : "l"(p));
    return a;
}
__device__ __forceinline__ void bsplit(float x, __nv_bfloat16& h, __nv_bfloat16& m) {
    h = __float2bfloat16(x);
    m = __float2bfloat16(x - __bfloat162float(h));
}
__device__ __forceinline__ void ldsm4(uint32_t a, uint32_t* r) {
    asm volatile("ldmatrix.sync.aligned.m8n8.x4.shared.b16 {%0,%1,%2,%3}, [%4];"
                 : "=r"(r[0]), "=r"(r[1]), "=r"(r[2]), "=r"(r[3]) : "r"(a));
}
__device__ __forceinline__ void mma16816(float* c, const uint32_t* a, uint32_t b0, uint32_t b1) {
    asm volatile(
        "mma.sync.aligned.m16n8k16.row.col.f32.bf16.bf16.f32 "
        "{%0,%1,%2,%3}, {%4,%5,%6,%7}, {%8,%9}, {%0,%1,%2,%3};"
        : "+f"(c[0]), "+f"(c[1]), "+f"(c[2]), "+f"(c[3])
        : "r"(a[0]), "r"(a[1]), "r"(a[2]), "r"(a[3]), "r"(b0), "r"(b1));
}
__device__ __forceinline__ void cpasync16(uint32_t dst, const void* src, uint32_t sz) {
    asm volatile("cp.async.ca.shared.global [%0], [%1], 16, %2;"
                 :: "r"(dst), "l"(src), "r"(sz));
}

// ---------------- embedding gather (f32 + hi/mid bf16) ----------------
__global__ void gather_kernel(const int* __restrict__ words,
                              const float* __restrict__ emb,
                              float* __restrict__ outf,
                              __nv_bfloat16* __restrict__ outh,
                              __nv_bfloat16* __restrict__ outm, int nrows) {
    int idx = blockIdx.x * blockDim.x + threadIdx.x;
    int total = nrows * (ND / 4);
    if (idx >= total) return;
    int row = idx >> 6;
    int d4  = idx & 63;
    int w = words[row];
    float4 v = reinterpret_cast<const float4*>(emb)[(size_t)w * 64 + d4];
    size_t o = (size_t)row * ND + d4 * 4;
    *reinterpret_cast<float4*>(outf + o) = v;
    __nv_bfloat16 h0, h1, h2, h3, m0, m1, m2, m3;
    bsplit(v.x, h0, m0); bsplit(v.y, h1, m1); bsplit(v.z, h2, m2); bsplit(v.w, h3, m3);
    *reinterpret_cast<__nv_bfloat162*>(outh + o)     = __halves2bfloat162(h0, h1);
    *reinterpret_cast<__nv_bfloat162*>(outh + o + 2) = __halves2bfloat162(h2, h3);
    *reinterpret_cast<__nv_bfloat162*>(outm + o)     = __halves2bfloat162(m0, m1);
    *reinterpret_cast<__nv_bfloat162*>(outm + o + 2) = __halves2bfloat162(m2, m3);
}

// ---------------- weight transpose + split: W[k][d][c] -> Wt[lk][c][d] hi/mid ----------------
__global__ void wconv_kernel(const float* __restrict__ exp_w, const float* __restrict__ ref_w,
                             __nv_bfloat16* __restrict__ wh, __nv_bfloat16* __restrict__ wm) {
    __shared__ float t[32][33];
    int lk = blockIdx.x;                 // 0..29 = layer*3 + tap
    int d0 = blockIdx.y * 32;
    int c0 = blockIdx.z * 32;
    const float* src = (lk < 21) ? exp_w + (size_t)lk * (ND * TWO_D)
                                 : ref_w + (size_t)(lk - 21) * (ND * TWO_D);
    t[threadIdx.y][threadIdx.x] = src[(size_t)(d0 + threadIdx.y) * TWO_D + c0 + threadIdx.x];
    __syncthreads();
    float v = t[threadIdx.x][threadIdx.y];   // = src[d0+tx][c0+ty]
    size_t o = ((size_t)lk * TWO_D + c0 + threadIdx.y) * ND + d0 + threadIdx.x;
    __nv_bfloat16 h, m;
    bsplit(v, h, m);
    wh[o] = h;
    wm[o] = m;
}

// ---------------- mma.sync res-block ----------------
// CTA: 128 rows x 64 GLU pairs (=128 out chans: 64 a + 64 g). 8 warps (4M x 2N),
// warp tile 32x64. K: 3 taps x 256 = 48 stages of 16, double buffered cp.async.
// Split: acc = Ah*Bh + Ah*Bm + Am*Bh.
#define RB_STAGE 24576    // Ah 6K | Am 6K | Bh 6K | Bm 6K  (rows stride 48B)
#define RB_SMEM  67584    // epilogue f32 tile 128x132 overlays stages

__global__ __launch_bounds__(256)
void resblock_mma(const float* __restrict__ Xf,
                  const __nv_bfloat16* __restrict__ Xh, const __nv_bfloat16* __restrict__ Xm,
                  float* __restrict__ Yf,
                  __nv_bfloat16* __restrict__ Yh, __nv_bfloat16* __restrict__ Ym,
                  const __nv_bfloat16* __restrict__ Wth, const __nv_bfloat16* __restrict__ Wtm,
                  const float* __restrict__ bias, int L, int dil) {
    extern __shared__ char smem[];
    const uint32_t sb = smem_u32(smem);
    const int tid = threadIdx.x;
    const int lane = tid & 31;
    const int wid = tid >> 5;

    const int rowBase = blockIdx.x * 128;
    const int cBase = blockIdx.y * 64;     // pair base
    const int bb = rowBase / L;
    const int lBase = rowBase - bb * L;

    const int warpM = (wid & 3) * 32;
    const int warpN = (wid >> 2) * 64;

    // ldmatrix byte offsets within one tensor block
    int offA[2], offB[4];
    {
        int rsel = lane & 15, kby = (lane >> 4) * 16;
        offA[0] = (warpM + rsel) * 48 + kby;
        offA[1] = (warpM + 16 + rsel) * 48 + kby;
        int jm = lane >> 3;
        int nn = (jm >> 1) * 8 + (lane & 7);
        int kb2 = (jm & 1) * 16;
#pragma unroll
        for (int p = 0; p < 4; p++) offB[p] = (warpN + p * 16 + nn) * 48 + kb2;
    }

    // loader mapping: 256 threads -> (row, 16B-chunk)
    const int lr = tid >> 1;
    const int lch = tid & 1;
    const uint32_t ldst = sb + lr * 48 + lch * 16;
    const int lcB = (lr < 64) ? (cBase + lr) : (cBase + 192 + lr);  // a then g channels

    float acc[16][4];
#pragma unroll
    for (int i = 0; i < 16; i++)
#pragma unroll
        for (int j = 0; j < 4; j++) acc[i][j] = 0.f;

    auto issue = [&](int s, int buf) {
        const int tap = s >> 4;
        const int k0 = (s & 15) << 4;
        const int shift = (tap - 1) * dil;
        int p = lBase + lr + shift;
        uint32_t sz = (p >= 0 && p < L) ? 16u : 0u;
        int pc = p < 0 ? 0 : (p >= L ? L - 1 : p);
        size_t aoff = (size_t)(bb * L + pc) * ND + k0 + lch * 8;
        uint32_t base = ldst + buf * RB_STAGE;
        cpasync16(base, Xh + aoff, sz);
        cpasync16(base + 6144, Xm + aoff, sz);
        size_t boff = ((size_t)tap * TWO_D + lcB) * ND + k0 + lch * 8;
        cpasync16(base + 12288, Wth + boff, 16u);
        cpasync16(base + 18432, Wtm + boff, 16u);
        asm volatile("cp.async.commit_group;");
    };

    auto domma = [&](int buf) {
        uint32_t tb = sb + buf * RB_STAGE;
        uint32_t ah[2][4], am[2][4];
        ldsm4(tb + offA[0], ah[0]);
        ldsm4(tb + offA[1], ah[1]);
        ldsm4(tb + 6144 + offA[0], am[0]);
        ldsm4(tb + 6144 + offA[1], am[1]);
#pragma unroll
        for (int p = 0; p < 4; p++) {
            uint32_t bh[4], bm[4];
            ldsm4(tb + 12288 + offB[p], bh);
            ldsm4(tb + 18432 + offB[p], bm);
#pragma unroll
            for (int t = 0; t < 2; t++) {
                float* c0 = acc[t * 8 + 2 * p];
                float* c1 = acc[t * 8 + 2 * p + 1];
                mma16816(c0, ah[t], bh[0], bh[1]);
                mma16816(c0, ah[t], bm[0], bm[1]);
                mma16816(c0, am[t], bh[0], bh[1]);
                mma16816(c1, ah[t], bh[2], bh[3]);
                mma16816(c1, ah[t], bm[2], bm[3]);
                mma16816(c1, am[t], bh[2], bh[3]);
            }
        }
    };

    issue(0, 0);
    for (int s = 0; s < 48; s++) {
        if (s < 47) {
            issue(s + 1, (s + 1) & 1);
            asm volatile("cp.async.wait_group 1;");
        } else {
            asm volatile("cp.async.wait_group 0;");
        }
        __syncthreads();
        domma(s & 1);
        __syncthreads();
    }

    // ---- epilogue: stage accums through smem f32, fuse bias+GLU+residual+split ----
    float* sf = reinterpret_cast<float*>(smem);
#pragma unroll
    for (int t = 0; t < 2; t++)
#pragma unroll
        for (int j = 0; j < 8; j++) {
            int row0 = warpM + 16 * t + (lane >> 2);
            int col0 = warpN + 8 * j + 2 * (lane & 3);
            *reinterpret_cast<float2*>(&sf[row0 * 132 + col0]) =
                make_float2(acc[t * 8 + j][0], acc[t * 8 + j][1]);
            *reinterpret_cast<float2*>(&sf[(row0 + 8) * 132 + col0]) =
                make_float2(acc[t * 8 + j][2], acc[t * 8 + j][3]);
        }
    __syncthreads();

    {
        const int rr = tid >> 1;
        const int j0 = (tid & 1) * 32;
        const size_t rowg = (size_t)rowBase + rr;
        const float* xr = Xf + rowg * ND;
        float* yr = Yf + rowg * ND;
        __nv_bfloat16* yh = Yh + rowg * ND;
        __nv_bfloat16* ym = Ym + rowg * ND;
#pragma unroll
        for (int jj = 0; jj < 32; jj += 4) {
            int c = cBase + j0 + jj;
            float4 av = *reinterpret_cast<const float4*>(&sf[rr * 132 + j0 + jj]);
            float4 gv = *reinterpret_cast<const float4*>(&sf[rr * 132 + 64 + j0 + jj]);
            float4 xv = *reinterpret_cast<const float4*>(xr + c);
            float4 ba = *reinterpret_cast<const float4*>(bias + c);
            float4 bg = *reinterpret_cast<const float4*>(bias + 256 + c);
            float4 y;
            y.x = xv.x + (av.x + ba.x) * (1.f / (1.f + expf(-(gv.x + bg.x))));
            y.y = xv.y + (av.y + ba.y) * (1.f / (1.f + expf(-(gv.y + bg.y))));
            y.z = xv.z + (av.z + ba.z) * (1.f / (1.f + expf(-(gv.z + bg.z))));
            y.w = xv.w + (av.w + ba.w) * (1.f / (1.f + expf(-(gv.w + bg.w))));
            *reinterpret_cast<float4*>(yr + c) = y;
            __nv_bfloat16 h0, h1, h2, h3, m0, m1, m2, m3;
            bsplit(y.x, h0, m0); bsplit(y.y, h1, m1);
            bsplit(y.z, h2, m2); bsplit(y.w, h3, m3);
            *reinterpret_cast<__nv_bfloat162*>(yh + c)     = __halves2bfloat162(h0, h1);
            *reinterpret_cast<__nv_bfloat162*>(yh + c + 2) = __halves2bfloat162(h2, h3);
            *reinterpret_cast<__nv_bfloat162*>(ym + c)     = __halves2bfloat162(m0, m1);
            *reinterpret_cast<__nv_bfloat162*>(ym + c + 2) = __halves2bfloat162(m2, m3);
        }
    }
}

// ---------------- squared norms per row ----------------
__global__ void norm_kernel(const float* __restrict__ X, float* __restrict__ out) {
    int row = blockIdx.x;
    int tid = threadIdx.x;
    float4 v = reinterpret_cast<const float4*>(X + (size_t)row * ND)[tid];
    float s = v.x * v.x + v.y * v.y + v.z * v.z + v.w * v.w;
#pragma unroll
    for (int off = 16; off > 0; off >>= 1)
        s += __shfl_down_sync(0xFFFFFFFFu, s, off);
    __shared__ float ws[2];
    if ((tid & 31) == 0) ws[tid >> 5] = s;
    __syncthreads();
    if (tid == 0) out[row] = ws[0] + ws[1];
}

// ---------------- distance + row-max ----------------
#define DA 64
#define DT 64
#define DS_STRIDE 68

__global__ __launch_bounds__(256)
void dist_kernel(const float* __restrict__ art, const float* __restrict__ tpl,
                 const float* __restrict__ a2, const float* __restrict__ t2,
                 const float* __restrict__ am, const float* __restrict__ tm,
                 float* __restrict__ rowmax_out) {
    const int b = blockIdx.y;
    const int aBase = blockIdx.x * DA;
    __shared__ float As[32 * DS_STRIDE];
    __shared__ float Ts[32 * DS_STRIDE];
    __shared__ int rmax[DA];

    const int tid = threadIdx.x;
    if (tid < DA) rmax[tid] = 0;

    const int ag = tid >> 4, tg = tid & 15;
    const int ar0 = ag * 4, tc0 = tg * 4;

    float thmax[4] = {0.f, 0.f, 0.f, 0.f};

    float a2v[4], amv[4];
#pragma unroll
    for (int i = 0; i < 4; i++) {
        a2v[i] = a2[b * NA + aBase + ar0 + i];
        amv[i] = am[b * NA + aBase + ar0 + i];
    }

    for (int tTile = 0; tTile < NT / DT; tTile++) {
        float acc[4][4];
#pragma unroll
        for (int i = 0; i < 4; i++)
#pragma unroll
            for (int j = 0; j < 4; j++) acc[i][j] = 0.f;

        for (int dBase = 0; dBase < ND; dBase += 32) {
            __syncthreads();
#pragma unroll
            for (int q = 0; q < 2; q++) {
                int f4id = tid + q * 256;
                int m = f4id >> 3;
                int dq = (f4id & 7) * 4;
                float4 va = *reinterpret_cast<const float4*>(
                    art + ((size_t)(b * NA + aBase + m)) * ND + dBase + dq);
                float4 vt = *reinterpret_cast<const float4*>(
                    tpl + ((size_t)(b * NT + tTile * DT + m)) * ND + dBase + dq);
                As[(dq + 0) * DS_STRIDE + m] = va.x;
                As[(dq + 1) * DS_STRIDE + m] = va.y;
                As[(dq + 2) * DS_STRIDE + m] = va.z;
                As[(dq + 3) * DS_STRIDE + m] = va.w;
                Ts[(dq + 0) * DS_STRIDE + m] = vt.x;
                Ts[(dq + 1) * DS_STRIDE + m] = vt.y;
                Ts[(dq + 2) * DS_STRIDE + m] = vt.z;
                Ts[(dq + 3) * DS_STRIDE + m] = vt.w;
            }
            __syncthreads();
#pragma unroll
            for (int dd = 0; dd < 32; dd++) {
                float4 ra = *reinterpret_cast<const float4*>(&As[dd * DS_STRIDE + ar0]);
                float4 rt = *reinterpret_cast<const float4*>(&Ts[dd * DS_STRIDE + tc0]);
                float av[4] = {ra.x, ra.y, ra.z, ra.w};
                float tv[4] = {rt.x, rt.y, rt.z, rt.w};
#pragma unroll
                for (int i = 0; i < 4; i++)
#pragma unroll
                    for (int j = 0; j < 4; j++)
                        acc[i][j] = fmaf(av[i], tv[j], acc[i][j]);
            }
        }
#pragma unroll
        for (int j = 0; j < 4; j++) {
            int t = tTile * DT + tc0 + j;
            float t2v = t2[b * NT + t];
            float tmv = tm[b * NT + t];
#pragma unroll
            for (int i = 0; i < 4; i++) {
                float dist = a2v[i] + t2v - 2.f * acc[i][j];
                dist = fmaxf(dist, 0.f);
                float s = expf(-dist) * amv[i] * tmv;
                thmax[i] = fmaxf(thmax[i], s);
            }
        }
    }
#pragma unroll
    for (int i = 0; i < 4; i++)
        atomicMax(&rmax[ar0 + i], __float_as_int(thmax[i]));
    __syncthreads();
    if (tid < DA)
        rowmax_out[b * NA + aBase + tid] = __int_as_float(rmax[tid]);
}

// ---------------- top-10 + MLP ----------------
__global__ void topk_mlp_kernel(const float* __restrict__ rowmax,
                                const float* __restrict__ ff1w,
                                const float* __restrict__ ff1b,
                                const float* __restrict__ ff2w,
                                const float* __restrict__ ff2b,
                                float* __restrict__ out) {
    int b = blockIdx.x;
    __shared__ float vals[NA];
    __shared__ float sv[256];
    __shared__ int si[256];
    __shared__ float top[10];
    int tid = threadIdx.x;
#pragma unroll
    for (int q = 0; q < 4; q++) vals[tid + q * 256] = rowmax[b * NA + tid + q * 256];
    __syncthreads();
    for (int it = 0; it < 10; it++) {
        float best = -1.f;
        int bi = 0;
        for (int i = tid; i < NA; i += 256) {
            if (vals[i] > best) { best = vals[i]; bi = i; }
        }
        sv[tid] = best;
        si[tid] = bi;
        __syncthreads();
        for (int off = 128; off > 0; off >>= 1) {
            if (tid < off) {
                if (sv[tid + off] > sv[tid]) { sv[tid] = sv[tid + off]; si[tid] = si[tid + off]; }
            }
            __syncthreads();
        }
        if (tid == 0) { top[it] = sv[0]; vals[si[0]] = -1.f; }
        __syncthreads();
    }
    if (tid == 0) {
        float o = ff2b[0];
        for (int j = 0; j < 10; j++) {
            float h = ff1b[j];
            for (int i = 0; i < 10; i++) h += top[i] * ff1w[i * 10 + j];
            h = fmaxf(h, 0.f);
            o += h * ff2w[j];
        }
        out[b] = o;
    }
}

// ---------------- launcher ----------------
extern "C" void kernel_launch(void* const* d_in, const int* in_sizes, int n_in,
                              void* d_out, int out_size) {
    const int* art_w   = (const int*)d_in[0];
    const int* tpl_w   = (const int*)d_in[2];
    const float* am    = (const float*)d_in[4];
    const float* tm    = (const float*)d_in[5];
    const float* emb   = (const float*)d_in[6];
    const float* exp_w = (const float*)d_in[7];
    const float* exp_b = (const float*)d_in[8];
    const float* ref_w = (const float*)d_in[9];
    const float* ref_b = (const float*)d_in[10];
    const float* ff1w  = (const float*)d_in[11];
    const float* ff1b  = (const float*)d_in[12];
    const float* ff2w  = (const float*)d_in[13];
    const float* ff2b  = (const float*)d_in[14];

    float *artf, *tplf, *a2p, *t2p, *rmp;
    __nv_bfloat16 *arth, *artm, *tplh, *tplm, *wth, *wtm;
    cudaGetSymbolAddress((void**)&artf, g_art);
    cudaGetSymbolAddress((void**)&tplf, g_tpl);
    cudaGetSymbolAddress((void**)&arth, g_art_h);
    cudaGetSymbolAddress((void**)&artm, g_art_m);
    cudaGetSymbolAddress((void**)&tplh, g_tpl_h);
    cudaGetSymbolAddress((void**)&tplm, g_tpl_m);
    cudaGetSymbolAddress((void**)&wth, g_wth);
    cudaGetSymbolAddress((void**)&wtm, g_wtm);
    cudaGetSymbolAddress((void**)&a2p, g_a2);
    cudaGetSymbolAddress((void**)&t2p, g_t2);
    cudaGetSymbolAddress((void**)&rmp, g_rowmax);

    const size_t ASZ = (size_t)NB * NA * ND;
    const size_t TSZ = (size_t)NB * NT * ND;
    float* af[2] = {artf, artf + ASZ};
    float* tf[2] = {tplf, tplf + TSZ};
    __nv_bfloat16* ah[2] = {arth, arth + ASZ};
    __nv_bfloat16* amid[2] = {artm, artm + ASZ};
    __nv_bfloat16* th[2] = {tplh, tplh + TSZ};
    __nv_bfloat16* tmid[2] = {tplm, tplm + TSZ};

    static int attr_set = 0;
    cudaFuncSetAttribute(resblock_mma, cudaFuncAttributeMaxDynamicSharedMemorySize, RB_SMEM);
    (void)attr_set;

    wconv_kernel<<<dim3(30, 8, 16), dim3(32, 32)>>>(exp_w, ref_w, wth, wtm);
    gather_kernel<<<(NB * NA * 64 + 255) / 256, 256>>>(art_w, emb, af[0], ah[0], amid[0], NB * NA);
    gather_kernel<<<(NB * NT * 64 + 255) / 256, 256>>>(tpl_w, emb, tf[0], th[0], tmid[0], NB * NT);

    const int dils[10] = {1, 2, 4, 8, 16, 32, 32, 1, 1, 1};
    int cur = 0;
    for (int i = 0; i < 10; i++) {
        const __nv_bfloat16* wh = wth + (size_t)i * 3 * TWO_D * ND;
        const __nv_bfloat16* wm = wtm + (size_t)i * 3 * TWO_D * ND;
        const float* bias = (i < 7) ? exp_b + (size_t)i * TWO_D
                                    : ref_b + (size_t)(i - 7) * TWO_D;
        resblock_mma<<<dim3((NB * NA) / 128, 4), 256, RB_SMEM>>>(
            af[cur], ah[cur], amid[cur], af[1 - cur], ah[1 - cur], amid[1 - cur],
            wh, wm, bias, NA, dils[i]);
        resblock_mma<<<dim3((NB * NT) / 128, 4), 256, RB_SMEM>>>(
            tf[cur], th[cur], tmid[cur], tf[1 - cur], th[1 - cur], tmid[1 - cur],
            wh, wm, bias, NT, dils[i]);
        cur ^= 1;
    }
    // 10 flips -> final tensors back in buffer 0

    norm_kernel<<<NB * NA, 64>>>(af[cur], a2p);
    norm_kernel<<<NB * NT, 64>>>(tf[cur], t2p);

    dist_kernel<<<dim3(NA / DA, NB), 256>>>(af[cur], tf[cur], a2p, t2p, am, tm, rmp);

    topk_mlp_kernel<<<NB, 256>>>(rmp, ff1w, ff1b, ff2w, ff2b, (float*)d_out);
}

// round 4
// speedup vs baseline: 2.2296x; 1.1966x over previous
#include <cuda_runtime.h>
#include <cuda_bf16.h>
#include <math.h>
#include <stdint.h>

// Problem constants
#define NB 16
#define NA 1024
#define NT 512
#define ND 256
#define TWO_D 512

// ---------------- scratch (no allocations allowed) ----------------
__device__ float g_art[2][NB * NA * ND];
__device__ float g_tpl[2][NB * NT * ND];
__device__ __nv_bfloat16 g_art_h[2][NB * NA * ND];
__device__ __nv_bfloat16 g_art_m[2][NB * NA * ND];
__device__ __nv_bfloat16 g_tpl_h[2][NB * NT * ND];
__device__ __nv_bfloat16 g_tpl_m[2][NB * NT * ND];
__device__ __nv_bfloat16 g_wth[10 * 3 * TWO_D * ND];
__device__ __nv_bfloat16 g_wtm[10 * 3 * TWO_D * ND];
__device__ float g_a2[NB * NA];
__device__ float g_t2[NB * NT];
__device__ float g_rowmax[NB * NA];

// ---------------- helpers ----------------
__device__ __forceinline__ uint32_t smem_u32(const void* p) {
    uint32_t a;
    asm("{ .reg .u64 t; cvta.to.shared.u64 t, %1; cvt.u32.u64 %0, t; }" : "=r"(a) : "l"(p));
    return a;
}
__device__ __forceinline__ void bsplit(float x, __nv_bfloat16& h, __nv_bfloat16& m) {
    h = __float2bfloat16(x);
    m = __float2bfloat16(x - __bfloat162float(h));
}
__device__ __forceinline__ void ldsm4(uint32_t a, uint32_t* r) {
    asm volatile("ldmatrix.sync.aligned.m8n8.x4.shared.b16 {%0,%1,%2,%3}, [%4];"
                 : "=r"(r[0]), "=r"(r[1]), "=r"(r[2]), "=r"(r[3]) : "r"(a));
}
__device__ __forceinline__ void mma16816(float* c, const uint32_t* a, uint32_t b0, uint32_t b1) {
    asm volatile(
        "mma.sync.aligned.m16n8k16.row.col.f32.bf16.bf16.f32 "
        "{%0,%1,%2,%3}, {%4,%5,%6,%7}, {%8,%9}, {%0,%1,%2,%3};"
        : "+f"(c[0]), "+f"(c[1]), "+f"(c[2]), "+f"(c[3])
        : "r"(a[0]), "r"(a[1]), "r"(a[2]), "r"(a[3]), "r"(b0), "r"(b1));
}
__device__ __forceinline__ void cpasync16(uint32_t dst, const void* src, uint32_t sz) {
    asm volatile("cp.async.ca.shared.global [%0], [%1], 16, %2;"
                 :: "r"(dst), "l"(src), "r"(sz));
}

// ---------------- embedding gather (f32 + hi/mid bf16) ----------------
__global__ void gather_kernel(const int* __restrict__ words,
                              const float* __restrict__ emb,
                              float* __restrict__ outf,
                              __nv_bfloat16* __restrict__ outh,
                              __nv_bfloat16* __restrict__ outm, int nrows) {
    int idx = blockIdx.x * blockDim.x + threadIdx.x;
    int total = nrows * (ND / 4);
    if (idx >= total) return;
    int row = idx >> 6;
    int d4  = idx & 63;
    int w = words[row];
    float4 v = reinterpret_cast<const float4*>(emb)[(size_t)w * 64 + d4];
    size_t o = (size_t)row * ND + d4 * 4;
    *reinterpret_cast<float4*>(outf + o) = v;
    __nv_bfloat16 h0, h1, h2, h3, m0, m1, m2, m3;
    bsplit(v.x, h0, m0); bsplit(v.y, h1, m1); bsplit(v.z, h2, m2); bsplit(v.w, h3, m3);
    *reinterpret_cast<__nv_bfloat162*>(outh + o)     = __halves2bfloat162(h0, h1);
    *reinterpret_cast<__nv_bfloat162*>(outh + o + 2) = __halves2bfloat162(h2, h3);
    *reinterpret_cast<__nv_bfloat162*>(outm + o)     = __halves2bfloat162(m0, m1);
    *reinterpret_cast<__nv_bfloat162*>(outm + o + 2) = __halves2bfloat162(m2, m3);
}

// ---------------- weight transpose + split: W[k][d][c] -> Wt[lk][c][d] hi/mid ----------------
__global__ void wconv_kernel(const float* __restrict__ exp_w, const float* __restrict__ ref_w,
                             __nv_bfloat16* __restrict__ wh, __nv_bfloat16* __restrict__ wm) {
    __shared__ float t[32][33];
    int lk = blockIdx.x;
    int d0 = blockIdx.y * 32;
    int c0 = blockIdx.z * 32;
    const float* src = (lk < 21) ? exp_w + (size_t)lk * (ND * TWO_D)
                                 : ref_w + (size_t)(lk - 21) * (ND * TWO_D);
    t[threadIdx.y][threadIdx.x] = src[(size_t)(d0 + threadIdx.y) * TWO_D + c0 + threadIdx.x];
    __syncthreads();
    float v = t[threadIdx.x][threadIdx.y];
    size_t o = ((size_t)lk * TWO_D + c0 + threadIdx.y) * ND + d0 + threadIdx.x;
    __nv_bfloat16 h, m;
    bsplit(v, h, m);
    wh[o] = h;
    wm[o] = m;
}

// ---------------- mma.sync res-block v2 ----------------
// CTA 128 rows x 128 chans (64 a + 64 g). 8 warps = 2M(64) x 4N(32).
// K-stage 32, 24 stages (3 taps x 8), 3-deep cp.async ring, 1 sync/stage.
// Smem row = 64B (4 x 16B chunks), swizzle: chunk ^= (row>>1)&3.
// Split: acc = Ah*Bh + Ah*Bm + Am*Bh.
#define RB_STAGE 32768  // Ah 8K | Am 8K | Bh 8K | Bm 8K
#define RB_SMEM  98304  // 3 stages; epilogue f32 tile 128x132 (67.6K) overlays

__global__ __launch_bounds__(256, 2)
void resblock_mma(const float* __restrict__ ArtF,
                  const __nv_bfloat16* __restrict__ ArtH, const __nv_bfloat16* __restrict__ ArtM,
                  float* __restrict__ ArtOF, __nv_bfloat16* __restrict__ ArtOH,
                  __nv_bfloat16* __restrict__ ArtOM,
                  const float* __restrict__ TplF,
                  const __nv_bfloat16* __restrict__ TplH, const __nv_bfloat16* __restrict__ TplM,
                  float* __restrict__ TplOF, __nv_bfloat16* __restrict__ TplOH,
                  __nv_bfloat16* __restrict__ TplOM,
                  const __nv_bfloat16* __restrict__ Wth, const __nv_bfloat16* __restrict__ Wtm,
                  const float* __restrict__ bias, int dil) {
    extern __shared__ char smem[];
    const uint32_t sb = smem_u32(smem);
    const int tid = threadIdx.x;
    const int lane = tid & 31;
    const int wid = tid >> 5;

    const bool isA = blockIdx.x < 128;
    const int mb = isA ? blockIdx.x : (blockIdx.x - 128);
    const int L = isA ? NA : NT;
    const __nv_bfloat16* Xh = isA ? ArtH : TplH;
    const __nv_bfloat16* Xm = isA ? ArtM : TplM;
    const float* Xf = isA ? ArtF : TplF;
    float* Yf = isA ? ArtOF : TplOF;
    __nv_bfloat16* Yh = isA ? ArtOH : TplOH;
    __nv_bfloat16* Ym = isA ? ArtOM : TplOM;

    const int rowBase = mb * 128;
    const int pairBase = blockIdx.y * 64;
    const int bb = rowBase / L;
    const int lBase = rowBase - bb * L;

    const int warpM = (wid & 1) * 64;
    const int warpN = (wid >> 1) * 32;

    // precomputed ldmatrix per-lane addressing
    // A: rowA(mt) = warpM + mt*16 + (lane&15); chunk base = lane>>4
    uint32_t offA[4];
    int swzA[4];
    {
        int r15 = lane & 15;
#pragma unroll
        for (int mt = 0; mt < 4; mt++) {
            int r = warpM + mt * 16 + r15;
            offA[mt] = r * 64;
            swzA[mt] = (r >> 1) & 3;
        }
    }
    const int cbA = lane >> 4;
    // B: rowB(nt) = warpN + nt*16 + (jm>>1)*8 + (lane&7); chunk base = jm&1
    uint32_t offB[2];
    int swzB[2];
    const int jm = lane >> 3;
    const int cbB = jm & 1;
    {
        int rb = (jm >> 1) * 8 + (lane & 7);
#pragma unroll
        for (int nt = 0; nt < 2; nt++) {
            int r = warpN + nt * 16 + rb;
            offB[nt] = r * 64;
            swzB[nt] = (r >> 1) & 3;
        }
    }

    float acc[4][4][4];
#pragma unroll
    for (int i = 0; i < 4; i++)
#pragma unroll
        for (int j = 0; j < 4; j++)
#pragma unroll
            for (int q = 0; q < 4; q++) acc[i][j][q] = 0.f;

    // loader: 256 threads x 2 chunks per array per stage
    auto issue = [&](int s) {
        if (s < 24) {
            const int buf = s - (s / 3) * 3;
            const uint32_t base = sb + buf * RB_STAGE;
            const int tap = s >> 3;
            const int k0 = (s & 7) << 5;
            const int shift = (tap - 1) * dil;
#pragma unroll
            for (int q = 0; q < 2; q++) {
                int idx = tid + q * 256;        // 0..511
                int row = idx >> 2;
                int kc = idx & 3;
                int kcs = kc ^ ((row >> 1) & 3);
                uint32_t dst = base + row * 64 + kcs * 16;
                // A
                int p = lBase + row + shift;
                uint32_t sz = (p >= 0 && p < L) ? 16u : 0u;
                int pc = p < 0 ? 0 : (p >= L ? L - 1 : p);
                size_t aoff = (size_t)(bb * L + pc) * ND + k0 + kc * 8;
                cpasync16(dst, Xh + aoff, sz);
                cpasync16(dst + 8192, Xm + aoff, sz);
                // B
                int chan = (row < 64) ? (pairBase + row) : (256 + pairBase + row - 64);
                size_t boff = ((size_t)tap * TWO_D + chan) * ND + k0 + kc * 8;
                cpasync16(dst + 16384, Wth + boff, 16u);
                cpasync16(dst + 24576, Wtm + boff, 16u);
            }
        }
        asm volatile("cp.async.commit_group;");
    };

    auto domma = [&](int buf) {
        const uint32_t base = sb + buf * RB_STAGE;
#pragma unroll
        for (int h = 0; h < 2; h++) {           // k16 halves of the 32-wide stage
            uint32_t bh[2][4], bm[2][4];
#pragma unroll
            for (int nt = 0; nt < 2; nt++) {
                uint32_t a = base + offB[nt] + (uint32_t)(((cbB + 2 * h) ^ swzB[nt]) * 16);
                ldsm4(a + 16384, bh[nt]);
                ldsm4(a + 24576, bm[nt]);
            }
#pragma unroll
            for (int mt = 0; mt < 4; mt++) {
                uint32_t a = base + offA[mt] + (uint32_t)(((cbA + 2 * h) ^ swzA[mt]) * 16);
                uint32_t ah[4], am[4];
                ldsm4(a, ah);
                ldsm4(a + 8192, am);
#pragma unroll
                for (int nt = 0; nt < 2; nt++) {
                    float* c0 = acc[mt][2 * nt];
                    float* c1 = acc[mt][2 * nt + 1];
                    mma16816(c0, ah, bh[nt][0], bh[nt][1]);
                    mma16816(c0, ah, bm[nt][0], bm[nt][1]);
                    mma16816(c0, am, bh[nt][0], bh[nt][1]);
                    mma16816(c1, ah, bh[nt][2], bh[nt][3]);
                    mma16816(c1, ah, bm[nt][2], bm[nt][3]);
                    mma16816(c1, am, bh[nt][2], bh[nt][3]);
                }
            }
        }
    };

    issue(0);
    issue(1);
    int buf = 0;
    for (int s = 0; s < 24; s++) {
        asm volatile("cp.async.wait_group 1;");
        __syncthreads();
        issue(s + 2);
        domma(buf);
        buf = (buf == 2) ? 0 : buf + 1;
    }
    __syncthreads();

    // ---- epilogue: accums -> smem f32, then bias+GLU+residual+split ----
    float* sf = reinterpret_cast<float*>(smem);
#pragma unroll
    for (int mt = 0; mt < 4; mt++)
#pragma unroll
        for (int nj = 0; nj < 4; nj++) {
            int r0 = warpM + mt * 16 + (lane >> 2);
            int c0 = warpN + nj * 8 + 2 * (lane & 3);
            *reinterpret_cast<float2*>(&sf[r0 * 132 + c0]) =
                make_float2(acc[mt][nj][0], acc[mt][nj][1]);
            *reinterpret_cast<float2*>(&sf[(r0 + 8) * 132 + c0]) =
                make_float2(acc[mt][nj][2], acc[mt][nj][3]);
        }
    __syncthreads();

    {
        const int rr = tid >> 1;
        const int j0 = (tid & 1) * 32;
        const size_t rowg = (size_t)rowBase + rr;
        const float* xr = Xf + rowg * ND;
        float* yr = Yf + rowg * ND;
        __nv_bfloat16* yh = Yh + rowg * ND;
        __nv_bfloat16* ym = Ym + rowg * ND;
#pragma unroll
        for (int jj = 0; jj < 32; jj += 4) {
            int c = pairBase + j0 + jj;
            float4 av = *reinterpret_cast<const float4*>(&sf[rr * 132 + j0 + jj]);
            float4 gv = *reinterpret_cast<const float4*>(&sf[rr * 132 + 64 + j0 + jj]);
            float4 xv = *reinterpret_cast<const float4*>(xr + c);
            float4 ba = *reinterpret_cast<const float4*>(bias + c);
            float4 bg = *reinterpret_cast<const float4*>(bias + 256 + c);
            float4 y;
            y.x = xv.x + (av.x + ba.x) * (1.f / (1.f + expf(-(gv.x + bg.x))));
            y.y = xv.y + (av.y + ba.y) * (1.f / (1.f + expf(-(gv.y + bg.y))));
            y.z = xv.z + (av.z + ba.z) * (1.f / (1.f + expf(-(gv.z + bg.z))));
            y.w = xv.w + (av.w + ba.w) * (1.f / (1.f + expf(-(gv.w + bg.w))));
            *reinterpret_cast<float4*>(yr + c) = y;
            __nv_bfloat16 h0, h1, h2, h3, m0, m1, m2, m3;
            bsplit(y.x, h0, m0); bsplit(y.y, h1, m1);
            bsplit(y.z, h2, m2); bsplit(y.w, h3, m3);
            *reinterpret_cast<__nv_bfloat162*>(yh + c)     = __halves2bfloat162(h0, h1);
            *reinterpret_cast<__nv_bfloat162*>(yh + c + 2) = __halves2bfloat162(h2, h3);
            *reinterpret_cast<__nv_bfloat162*>(ym + c)     = __halves2bfloat162(m0, m1);
            *reinterpret_cast<__nv_bfloat162*>(ym + c + 2) = __halves2bfloat162(m2, m3);
        }
    }
}

// ---------------- squared norms per row ----------------
__global__ void norm_kernel(const float* __restrict__ X, float* __restrict__ out) {
    int row = blockIdx.x;
    int tid = threadIdx.x;
    float4 v = reinterpret_cast<const float4*>(X + (size_t)row * ND)[tid];
    float s = v.x * v.x + v.y * v.y + v.z * v.z + v.w * v.w;
#pragma unroll
    for (int off = 16; off > 0; off >>= 1)
        s += __shfl_down_sync(0xFFFFFFFFu, s, off);
    __shared__ float ws[2];
    if ((tid & 31) == 0) ws[tid >> 5] = s;
    __syncthreads();
    if (tid == 0) out[row] = ws[0] + ws[1];
}

// ---------------- distance + row-max ----------------
#define DA 64
#define DT 64
#define DS_STRIDE 68

__global__ __launch_bounds__(256)
void dist_kernel(const float* __restrict__ art, const float* __restrict__ tpl,
                 const float* __restrict__ a2, const float* __restrict__ t2,
                 const float* __restrict__ am, const float* __restrict__ tm,
                 float* __restrict__ rowmax_out) {
    const int b = blockIdx.y;
    const int aBase = blockIdx.x * DA;
    __shared__ float As[32 * DS_STRIDE];
    __shared__ float Ts[32 * DS_STRIDE];
    __shared__ int rmax[DA];

    const int tid = threadIdx.x;
    if (tid < DA) rmax[tid] = 0;

    const int ag = tid >> 4, tg = tid & 15;
    const int ar0 = ag * 4, tc0 = tg * 4;

    float thmax[4] = {0.f, 0.f, 0.f, 0.f};

    float a2v[4], amv[4];
#pragma unroll
    for (int i = 0; i < 4; i++) {
        a2v[i] = a2[b * NA + aBase + ar0 + i];
        amv[i] = am[b * NA + aBase + ar0 + i];
    }

    for (int tTile = 0; tTile < NT / DT; tTile++) {
        float acc[4][4];
#pragma unroll
        for (int i = 0; i < 4; i++)
#pragma unroll
            for (int j = 0; j < 4; j++) acc[i][j] = 0.f;

        for (int dBase = 0; dBase < ND; dBase += 32) {
            __syncthreads();
#pragma unroll
            for (int q = 0; q < 2; q++) {
                int f4id = tid + q * 256;
                int m = f4id >> 3;
                int dq = (f4id & 7) * 4;
                float4 va = *reinterpret_cast<const float4*>(
                    art + ((size_t)(b * NA + aBase + m)) * ND + dBase + dq);
                float4 vt = *reinterpret_cast<const float4*>(
                    tpl + ((size_t)(b * NT + tTile * DT + m)) * ND + dBase + dq);
                As[(dq + 0) * DS_STRIDE + m] = va.x;
                As[(dq + 1) * DS_STRIDE + m] = va.y;
                As[(dq + 2) * DS_STRIDE + m] = va.z;
                As[(dq + 3) * DS_STRIDE + m] = va.w;
                Ts[(dq + 0) * DS_STRIDE + m] = vt.x;
                Ts[(dq + 1) * DS_STRIDE + m] = vt.y;
                Ts[(dq + 2) * DS_STRIDE + m] = vt.z;
                Ts[(dq + 3) * DS_STRIDE + m] = vt.w;
            }
            __syncthreads();
#pragma unroll
            for (int dd = 0; dd < 32; dd++) {
                float4 ra = *reinterpret_cast<const float4*>(&As[dd * DS_STRIDE + ar0]);
                float4 rt = *reinterpret_cast<const float4*>(&Ts[dd * DS_STRIDE + tc0]);
                float av[4] = {ra.x, ra.y, ra.z, ra.w};
                float tv[4] = {rt.x, rt.y, rt.z, rt.w};
#pragma unroll
                for (int i = 0; i < 4; i++)
#pragma unroll
                    for (int j = 0; j < 4; j++)
                        acc[i][j] = fmaf(av[i], tv[j], acc[i][j]);
            }
        }
#pragma unroll
        for (int j = 0; j < 4; j++) {
            int t = tTile * DT + tc0 + j;
            float t2v = t2[b * NT + t];
            float tmv = tm[b * NT + t];
#pragma unroll
            for (int i = 0; i < 4; i++) {
                float dist = a2v[i] + t2v - 2.f * acc[i][j];
                dist = fmaxf(dist, 0.f);
                float s = expf(-dist) * amv[i] * tmv;
                thmax[i] = fmaxf(thmax[i], s);
            }
        }
    }
#pragma unroll
    for (int i = 0; i < 4; i++)
        atomicMax(&rmax[ar0 + i], __float_as_int(thmax[i]));
    __syncthreads();
    if (tid < DA)
        rowmax_out[b * NA + aBase + tid] = __int_as_float(rmax[tid]);
}

// ---------------- top-10 + MLP ----------------
__global__ void topk_mlp_kernel(const float* __restrict__ rowmax,
                                const float* __restrict__ ff1w,
                                const float* __restrict__ ff1b,
                                const float* __restrict__ ff2w,
                                const float* __restrict__ ff2b,
                                float* __restrict__ out) {
    int b = blockIdx.x;
    __shared__ float vals[NA];
    __shared__ float sv[256];
    __shared__ int si[256];
    __shared__ float top[10];
    int tid = threadIdx.x;
#pragma unroll
    for (int q = 0; q < 4; q++) vals[tid + q * 256] = rowmax[b * NA + tid + q * 256];
    __syncthreads();
    for (int it = 0; it < 10; it++) {
        float best = -1.f;
        int bi = 0;
        for (int i = tid; i < NA; i += 256) {
            if (vals[i] > best) { best = vals[i]; bi = i; }
        }
        sv[tid] = best;
        si[tid] = bi;
        __syncthreads();
        for (int off = 128; off > 0; off >>= 1) {
            if (tid < off) {
                if (sv[tid + off] > sv[tid]) { sv[tid] = sv[tid + off]; si[tid] = si[tid + off]; }
            }
            __syncthreads();
        }
        if (tid == 0) { top[it] = sv[0]; vals[si[0]] = -1.f; }
        __syncthreads();
    }
    if (tid == 0) {
        float o = ff2b[0];
        for (int j = 0; j < 10; j++) {
            float h = ff1b[j];
            for (int i = 0; i < 10; i++) h += top[i] * ff1w[i * 10 + j];
            h = fmaxf(h, 0.f);
            o += h * ff2w[j];
        }
        out[b] = o;
    }
}

// ---------------- launcher ----------------
extern "C" void kernel_launch(void* const* d_in, const int* in_sizes, int n_in,
                              void* d_out, int out_size) {
    const int* art_w   = (const int*)d_in[0];
    const int* tpl_w   = (const int*)d_in[2];
    const float* am    = (const float*)d_in[4];
    const float* tm    = (const float*)d_in[5];
    const float* emb   = (const float*)d_in[6];
    const float* exp_w = (const float*)d_in[7];
    const float* exp_b = (const float*)d_in[8];
    const float* ref_w = (const float*)d_in[9];
    const float* ref_b = (const float*)d_in[10];
    const float* ff1w  = (const float*)d_in[11];
    const float* ff1b  = (const float*)d_in[12];
    const float* ff2w  = (const float*)d_in[13];
    const float* ff2b  = (const float*)d_in[14];

    float *artf, *tplf, *a2p, *t2p, *rmp;
    __nv_bfloat16 *arth, *artm, *tplh, *tplm, *wth, *wtm;
    cudaGetSymbolAddress((void**)&artf, g_art);
    cudaGetSymbolAddress((void**)&tplf, g_tpl);
    cudaGetSymbolAddress((void**)&arth, g_art_h);
    cudaGetSymbolAddress((void**)&artm, g_art_m);
    cudaGetSymbolAddress((void**)&tplh, g_tpl_h);
    cudaGetSymbolAddress((void**)&tplm, g_tpl_m);
    cudaGetSymbolAddress((void**)&wth, g_wth);
    cudaGetSymbolAddress((void**)&wtm, g_wtm);
    cudaGetSymbolAddress((void**)&a2p, g_a2);
    cudaGetSymbolAddress((void**)&t2p, g_t2);
    cudaGetSymbolAddress((void**)&rmp, g_rowmax);

    const size_t ASZ = (size_t)NB * NA * ND;
    const size_t TSZ = (size_t)NB * NT * ND;
    float* af[2] = {artf, artf + ASZ};
    float* tf[2] = {tplf, tplf + TSZ};
    __nv_bfloat16* ah[2] = {arth, arth + ASZ};
    __nv_bfloat16* amid[2] = {artm, artm + ASZ};
    __nv_bfloat16* th[2] = {tplh, tplh + TSZ};
    __nv_bfloat16* tmid[2] = {tplm, tplm + TSZ};

    cudaFuncSetAttribute(resblock_mma, cudaFuncAttributeMaxDynamicSharedMemorySize, RB_SMEM);

    wconv_kernel<<<dim3(30, 8, 16), dim3(32, 32)>>>(exp_w, ref_w, wth, wtm);
    gather_kernel<<<(NB * NA * 64 + 255) / 256, 256>>>(art_w, emb, af[0], ah[0], amid[0], NB * NA);
    gather_kernel<<<(NB * NT * 64 + 255) / 256, 256>>>(tpl_w, emb, tf[0], th[0], tmid[0], NB * NT);

    const int dils[10] = {1, 2, 4, 8, 16, 32, 32, 1, 1, 1};
    int cur = 0;
    for (int i = 0; i < 10; i++) {
        const __nv_bfloat16* wh = wth + (size_t)i * 3 * TWO_D * ND;
        const __nv_bfloat16* wm = wtm + (size_t)i * 3 * TWO_D * ND;
        const float* bias = (i < 7) ? exp_b + (size_t)i * TWO_D
                                    : ref_b + (size_t)(i - 7) * TWO_D;
        resblock_mma<<<dim3(128 + 64, 4), 256, RB_SMEM>>>(
            af[cur], ah[cur], amid[cur], af[1 - cur], ah[1 - cur], amid[1 - cur],
            tf[cur], th[cur], tmid[cur], tf[1 - cur], th[1 - cur], tmid[1 - cur],
            wh, wm, bias, dils[i]);
        cur ^= 1;
    }
    // 10 flips -> final tensors back in buffer 0

    norm_kernel<<<NB * NA, 64>>>(af[cur], a2p);
    norm_kernel<<<NB * NT, 64>>>(tf[cur], t2p);

    dist_kernel<<<dim3(NA / DA, NB), 256>>>(af[cur], tf[cur], a2p, t2p, am, tm, rmp);

    topk_mlp_kernel<<<NB, 256>>>(rmp, ff1w, ff1b, ff2w, ff2b, (float*)d_out);
}

// round 5
// speedup vs baseline: 2.6743x; 1.1994x over previous
#include <cuda_runtime.h>
#include <cuda_bf16.h>
#include <math.h>
#include <stdint.h>

// Problem constants
#define NB 16
#define NA 1024
#define NT 512
#define ND 256
#define TWO_D 512

// ---------------- scratch (no allocations allowed) ----------------
__device__ float g_art[2][NB * NA * ND];
__device__ float g_tpl[2][NB * NT * ND];
__device__ __nv_bfloat16 g_art_h[2][NB * NA * ND];
__device__ __nv_bfloat16 g_art_m[2][NB * NA * ND];
__device__ __nv_bfloat16 g_tpl_h[2][NB * NT * ND];
__device__ __nv_bfloat16 g_tpl_m[2][NB * NT * ND];
__device__ __nv_bfloat16 g_wth[10 * 3 * TWO_D * ND];
__device__ __nv_bfloat16 g_wtm[10 * 3 * TWO_D * ND];
__device__ float g_a2[NB * NA];
__device__ float g_t2[NB * NT];
__device__ float g_rowmax[NB * NA];

// ---------------- helpers ----------------
__device__ __forceinline__ uint32_t smem_u32(const void* p) {
    uint32_t a;
    asm("{ .reg .u64 t; cvta.to.shared.u64 t, %1; cvt.u32.u64 %0, t; }" : "=r"(a) : "l"(p));
    return a;
}
__device__ __forceinline__ void bsplit(float x, __nv_bfloat16& h, __nv_bfloat16& m) {
    h = __float2bfloat16(x);
    m = __float2bfloat16(x - __bfloat162float(h));
}
__device__ __forceinline__ void ldsm4(uint32_t a, uint32_t* r) {
    asm volatile("ldmatrix.sync.aligned.m8n8.x4.shared.b16 {%0,%1,%2,%3}, [%4];"
                 : "=r"(r[0]), "=r"(r[1]), "=r"(r[2]), "=r"(r[3]) : "r"(a));
}
__device__ __forceinline__ void mma16816(float* c, const uint32_t* a, uint32_t b0, uint32_t b1) {
    asm volatile(
        "mma.sync.aligned.m16n8k16.row.col.f32.bf16.bf16.f32 "
        "{%0,%1,%2,%3}, {%4,%5,%6,%7}, {%8,%9}, {%0,%1,%2,%3};"
        : "+f"(c[0]), "+f"(c[1]), "+f"(c[2]), "+f"(c[3])
        : "r"(a[0]), "r"(a[1]), "r"(a[2]), "r"(a[3]), "r"(b0), "r"(b1));
}
__device__ __forceinline__ void cpasync16(uint32_t dst, const void* src, uint32_t sz) {
    asm volatile("cp.async.cg.shared.global [%0], [%1], 16, %2;"
                 :: "r"(dst), "l"(src), "r"(sz));
}

// ---------------- embedding gather (f32 + hi/mid bf16) ----------------
__global__ void gather_kernel(const int* __restrict__ words,
                              const float* __restrict__ emb,
                              float* __restrict__ outf,
                              __nv_bfloat16* __restrict__ outh,
                              __nv_bfloat16* __restrict__ outm, int nrows) {
    int idx = blockIdx.x * blockDim.x + threadIdx.x;
    int total = nrows * (ND / 4);
    if (idx >= total) return;
    int row = idx >> 6;
    int d4  = idx & 63;
    int w = words[row];
    float4 v = reinterpret_cast<const float4*>(emb)[(size_t)w * 64 + d4];
    size_t o = (size_t)row * ND + d4 * 4;
    *reinterpret_cast<float4*>(outf + o) = v;
    __nv_bfloat16 h0, h1, h2, h3, m0, m1, m2, m3;
    bsplit(v.x, h0, m0); bsplit(v.y, h1, m1); bsplit(v.z, h2, m2); bsplit(v.w, h3, m3);
    *reinterpret_cast<__nv_bfloat162*>(outh + o)     = __halves2bfloat162(h0, h1);
    *reinterpret_cast<__nv_bfloat162*>(outh + o + 2) = __halves2bfloat162(h2, h3);
    *reinterpret_cast<__nv_bfloat162*>(outm + o)     = __halves2bfloat162(m0, m1);
    *reinterpret_cast<__nv_bfloat162*>(outm + o + 2) = __halves2bfloat162(m2, m3);
}

// ---------------- weight transpose + split: W[k][d][c] -> Wt[lk][c][d] hi/mid ----------------
__global__ void wconv_kernel(const float* __restrict__ exp_w, const float* __restrict__ ref_w,
                             __nv_bfloat16* __restrict__ wh, __nv_bfloat16* __restrict__ wm) {
    __shared__ float t[32][33];
    int lk = blockIdx.x;
    int d0 = blockIdx.y * 32;
    int c0 = blockIdx.z * 32;
    const float* src = (lk < 21) ? exp_w + (size_t)lk * (ND * TWO_D)
                                 : ref_w + (size_t)(lk - 21) * (ND * TWO_D);
    t[threadIdx.y][threadIdx.x] = src[(size_t)(d0 + threadIdx.y) * TWO_D + c0 + threadIdx.x];
    __syncthreads();
    float v = t[threadIdx.x][threadIdx.y];
    size_t o = ((size_t)lk * TWO_D + c0 + threadIdx.y) * ND + d0 + threadIdx.x;
    __nv_bfloat16 h, m;
    bsplit(v, h, m);
    wh[o] = h;
    wm[o] = m;
}

// ---------------- mma.sync res-block v3 ----------------
// CTA 128 rows x 64 GLU pairs. B smem rows interleaved (even=a-chan, odd=g-chan)
// so each mma C fragment holds (a,g) of the same output channel -> in-register GLU.
// 8 warps = 2M(64) x 4N(32). K-stage 32, 24 stages, 3-ring, 1 sync/stage.
// Fragment software pipelining: A groups double-buffered, prefetch before mma.
// Split: acc = Ah*Bh + Ah*Bm + Am*Bh.
#define RB_STAGE 32768  // Ah 8K | Am 8K | Bh 8K | Bm 8K
#define RB_SMEM  98304  // 3 stages

__global__ __launch_bounds__(256, 2)
void resblock_mma(const float* __restrict__ ArtF,
                  const __nv_bfloat16* __restrict__ ArtH, const __nv_bfloat16* __restrict__ ArtM,
                  float* __restrict__ ArtOF, __nv_bfloat16* __restrict__ ArtOH,
                  __nv_bfloat16* __restrict__ ArtOM,
                  const float* __restrict__ TplF,
                  const __nv_bfloat16* __restrict__ TplH, const __nv_bfloat16* __restrict__ TplM,
                  float* __restrict__ TplOF, __nv_bfloat16* __restrict__ TplOH,
                  __nv_bfloat16* __restrict__ TplOM,
                  const __nv_bfloat16* __restrict__ Wth, const __nv_bfloat16* __restrict__ Wtm,
                  const float* __restrict__ bias, int dil) {
    extern __shared__ char smem[];
    const uint32_t sb = smem_u32(smem);
    const int tid = threadIdx.x;
    const int lane = tid & 31;
    const int wid = tid >> 5;

    const bool isA = blockIdx.x < 128;
    const int mb = isA ? blockIdx.x : (blockIdx.x - 128);
    const int L = isA ? NA : NT;
    const __nv_bfloat16* Xh = isA ? ArtH : TplH;
    const __nv_bfloat16* Xm = isA ? ArtM : TplM;
    const float* Xf = isA ? ArtF : TplF;
    float* Yf = isA ? ArtOF : TplOF;
    __nv_bfloat16* Yh = isA ? ArtOH : TplOH;
    __nv_bfloat16* Ym = isA ? ArtOM : TplOM;

    const int rowBase = mb * 128;
    const int pairBase = blockIdx.y * 64;
    const int bb = rowBase / L;
    const int lBase = rowBase - bb * L;

    const int warpM = (wid & 1) * 64;
    const int warpN = (wid >> 1) * 32;

    // A ldmatrix addressing: rowA(mt) = warpM + mt*16 + (lane&15); chunk base lane>>4
    uint32_t offA[4];
    int swzA[4];
    {
        int r15 = lane & 15;
#pragma unroll
        for (int mt = 0; mt < 4; mt++) {
            int r = warpM + mt * 16 + r15;
            offA[mt] = r * 64;
            swzA[mt] = (r >> 1) & 3;
        }
    }
    const int cbA = lane >> 4;
    // B: rowB(nt) = warpN + nt*16 + (jm>>1)*8 + (lane&7); chunk base jm&1
    uint32_t offB[2];
    int swzB[2];
    const int jm = lane >> 3;
    const int cbB = jm & 1;
    {
        int rb = (jm >> 1) * 8 + (lane & 7);
#pragma unroll
        for (int nt = 0; nt < 2; nt++) {
            int r = warpN + nt * 16 + rb;
            offB[nt] = r * 64;
            swzB[nt] = (r >> 1) & 3;
        }
    }

    float acc[4][4][4];
#pragma unroll
    for (int i = 0; i < 4; i++)
#pragma unroll
        for (int j = 0; j < 4; j++)
#pragma unroll
            for (int q = 0; q < 4; q++) acc[i][j][q] = 0.f;

    auto issue = [&](int s) {
        if (s < 24) {
            const int buf = s - (s / 3) * 3;
            const uint32_t base = sb + buf * RB_STAGE;
            const int tap = s >> 3;
            const int k0 = (s & 7) << 5;
            const int shift = (tap - 1) * dil;
#pragma unroll
            for (int q = 0; q < 2; q++) {
                int idx = tid + q * 256;        // 0..511
                int row = idx >> 2;
                int kc = idx & 3;
                int kcs = kc ^ ((row >> 1) & 3);
                uint32_t dst = base + row * 64 + kcs * 16;
                // A
                int p = lBase + row + shift;
                uint32_t sz = (p >= 0 && p < L) ? 16u : 0u;
                int pc = p < 0 ? 0 : (p >= L ? L - 1 : p);
                size_t aoff = (size_t)(bb * L + pc) * ND + k0 + kc * 8;
                cpasync16(dst, Xh + aoff, sz);
                cpasync16(dst + 8192, Xm + aoff, sz);
                // B interleaved: even row -> a-chan, odd row -> g-chan
                int pr = pairBase + (row >> 1);
                int chan = (row & 1) ? (256 + pr) : pr;
                size_t boff = ((size_t)tap * TWO_D + chan) * ND + k0 + kc * 8;
                cpasync16(dst + 16384, Wth + boff, 16u);
                cpasync16(dst + 24576, Wtm + boff, 16u);
            }
        }
        asm volatile("cp.async.commit_group;");
    };

    auto domma = [&](int buf) {
        const uint32_t base = sb + buf * RB_STAGE;
        uint32_t bh[2][4], bm[2][4];
        uint32_t ah[2][4], am[2][4];
#pragma unroll
        for (int h = 0; h < 2; h++) {
            // B for this k16 half
#pragma unroll
            for (int nt = 0; nt < 2; nt++) {
                uint32_t a = base + offB[nt] + (uint32_t)(((cbB + 2 * h) ^ swzB[nt]) * 16);
                ldsm4(a + 16384, bh[nt]);
                ldsm4(a + 24576, bm[nt]);
            }
            // preload A group 0
            {
                uint32_t a = base + offA[0] + (uint32_t)(((cbA + 2 * h) ^ swzA[0]) * 16);
                ldsm4(a, ah[0]);
                ldsm4(a + 8192, am[0]);
            }
            int cur = 0;
#pragma unroll
            for (int mt = 0; mt < 4; mt++) {
                int nxt = cur ^ 1;
                if (mt < 3) {   // prefetch next A group while mma runs on current
                    uint32_t a = base + offA[mt + 1] +
                                 (uint32_t)(((cbA + 2 * h) ^ swzA[mt + 1]) * 16);
                    ldsm4(a, ah[nxt]);
                    ldsm4(a + 8192, am[nxt]);
                }
#pragma unroll
                for (int nt = 0; nt < 2; nt++) {
                    float* c0 = acc[mt][2 * nt];
                    float* c1 = acc[mt][2 * nt + 1];
                    mma16816(c0, ah[cur], bh[nt][0], bh[nt][1]);
                    mma16816(c0, ah[cur], bm[nt][0], bm[nt][1]);
                    mma16816(c0, am[cur], bh[nt][0], bh[nt][1]);
                    mma16816(c1, ah[cur], bh[nt][2], bh[nt][3]);
                    mma16816(c1, ah[cur], bm[nt][2], bm[nt][3]);
                    mma16816(c1, am[cur], bh[nt][2], bh[nt][3]);
                }
                cur = nxt;
            }
        }
    };

    issue(0);
    issue(1);
    int buf = 0;
    for (int s = 0; s < 24; s++) {
        asm volatile("cp.async.wait_group 1;");
        __syncthreads();
        issue(s + 2);
        domma(buf);
        buf = (buf == 2) ? 0 : buf + 1;
    }

    // ---- in-register epilogue: bias + GLU + residual + bf16 split ----
    {
        const int laneRow = lane >> 2;
        const int laneP = lane & 3;
        const int pB = pairBase + (warpN >> 1) + laneP;
#pragma unroll
        for (int nj = 0; nj < 4; nj++) {
            const int p = pB + nj * 4;
            const float ba = bias[p];
            const float bg = bias[256 + p];
#pragma unroll
            for (int mt = 0; mt < 4; mt++) {
                const int r0 = rowBase + warpM + mt * 16 + laneRow;
                const float* c = acc[mt][nj];
#pragma unroll
                for (int hrow = 0; hrow < 2; hrow++) {
                    const size_t o = (size_t)(r0 + 8 * hrow) * ND + p;
                    float a = c[2 * hrow] + ba;
                    float g = c[2 * hrow + 1] + bg;
                    float y = Xf[o] + a * (1.f / (1.f + expf(-g)));
                    Yf[o] = y;
                    __nv_bfloat16 hh, mm;
                    bsplit(y, hh, mm);
                    Yh[o] = hh;
                    Ym[o] = mm;
                }
            }
        }
    }
}

// ---------------- squared norms per row ----------------
__global__ void norm_kernel(const float* __restrict__ X, float* __restrict__ out) {
    int row = blockIdx.x;
    int tid = threadIdx.x;
    float4 v = reinterpret_cast<const float4*>(X + (size_t)row * ND)[tid];
    float s = v.x * v.x + v.y * v.y + v.z * v.z + v.w * v.w;
#pragma unroll
    for (int off = 16; off > 0; off >>= 1)
        s += __shfl_down_sync(0xFFFFFFFFu, s, off);
    __shared__ float ws[2];
    if ((tid & 31) == 0) ws[tid >> 5] = s;
    __syncthreads();
    if (tid == 0) out[row] = ws[0] + ws[1];
}

// ---------------- distance + row-max ----------------
#define DA 64
#define DT 64
#define DS_STRIDE 68

__global__ __launch_bounds__(256)
void dist_kernel(const float* __restrict__ art, const float* __restrict__ tpl,
                 const float* __restrict__ a2, const float* __restrict__ t2,
                 const float* __restrict__ am, const float* __restrict__ tm,
                 float* __restrict__ rowmax_out) {
    const int b = blockIdx.y;
    const int aBase = blockIdx.x * DA;
    __shared__ float As[32 * DS_STRIDE];
    __shared__ float Ts[32 * DS_STRIDE];
    __shared__ int rmax[DA];

    const int tid = threadIdx.x;
    if (tid < DA) rmax[tid] = 0;

    const int ag = tid >> 4, tg = tid & 15;
    const int ar0 = ag * 4, tc0 = tg * 4;

    float thmax[4] = {0.f, 0.f, 0.f, 0.f};

    float a2v[4], amv[4];
#pragma unroll
    for (int i = 0; i < 4; i++) {
        a2v[i] = a2[b * NA + aBase + ar0 + i];
        amv[i] = am[b * NA + aBase + ar0 + i];
    }

    for (int tTile = 0; tTile < NT / DT; tTile++) {
        float acc[4][4];
#pragma unroll
        for (int i = 0; i < 4; i++)
#pragma unroll
            for (int j = 0; j < 4; j++) acc[i][j] = 0.f;

        for (int dBase = 0; dBase < ND; dBase += 32) {
            __syncthreads();
#pragma unroll
            for (int q = 0; q < 2; q++) {
                int f4id = tid + q * 256;
                int m = f4id >> 3;
                int dq = (f4id & 7) * 4;
                float4 va = *reinterpret_cast<const float4*>(
                    art + ((size_t)(b * NA + aBase + m)) * ND + dBase + dq);
                float4 vt = *reinterpret_cast<const float4*>(
                    tpl + ((size_t)(b * NT + tTile * DT + m)) * ND + dBase + dq);
                As[(dq + 0) * DS_STRIDE + m] = va.x;
                As[(dq + 1) * DS_STRIDE + m] = va.y;
                As[(dq + 2) * DS_STRIDE + m] = va.z;
                As[(dq + 3) * DS_STRIDE + m] = va.w;
                Ts[(dq + 0) * DS_STRIDE + m] = vt.x;
                Ts[(dq + 1) * DS_STRIDE + m] = vt.y;
                Ts[(dq + 2) * DS_STRIDE + m] = vt.z;
                Ts[(dq + 3) * DS_STRIDE + m] = vt.w;
            }
            __syncthreads();
#pragma unroll
            for (int dd = 0; dd < 32; dd++) {
                float4 ra = *reinterpret_cast<const float4*>(&As[dd * DS_STRIDE + ar0]);
                float4 rt = *reinterpret_cast<const float4*>(&Ts[dd * DS_STRIDE + tc0]);
                float av[4] = {ra.x, ra.y, ra.z, ra.w};
                float tv[4] = {rt.x, rt.y, rt.z, rt.w};
#pragma unroll
                for (int i = 0; i < 4; i++)
#pragma unroll
                    for (int j = 0; j < 4; j++)
                        acc[i][j] = fmaf(av[i], tv[j], acc[i][j]);
            }
        }
#pragma unroll
        for (int j = 0; j < 4; j++) {
            int t = tTile * DT + tc0 + j;
            float t2v = t2[b * NT + t];
            float tmv = tm[b * NT + t];
#pragma unroll
            for (int i = 0; i < 4; i++) {
                float dist = a2v[i] + t2v - 2.f * acc[i][j];
                dist = fmaxf(dist, 0.f);
                float s = expf(-dist) * amv[i] * tmv;
                thmax[i] = fmaxf(thmax[i], s);
            }
        }
    }
#pragma unroll
    for (int i = 0; i < 4; i++)
        atomicMax(&rmax[ar0 + i], __float_as_int(thmax[i]));
    __syncthreads();
    if (tid < DA)
        rowmax_out[b * NA + aBase + tid] = __int_as_float(rmax[tid]);
}

// ---------------- top-10 + MLP ----------------
__global__ void topk_mlp_kernel(const float* __restrict__ rowmax,
                                const float* __restrict__ ff1w,
                                const float* __restrict__ ff1b,
                                const float* __restrict__ ff2w,
                                const float* __restrict__ ff2b,
                                float* __restrict__ out) {
    int b = blockIdx.x;
    __shared__ float vals[NA];
    __shared__ float sv[256];
    __shared__ int si[256];
    __shared__ float top[10];
    int tid = threadIdx.x;
#pragma unroll
    for (int q = 0; q < 4; q++) vals[tid + q * 256] = rowmax[b * NA + tid + q * 256];
    __syncthreads();
    for (int it = 0; it < 10; it++) {
        float best = -1.f;
        int bi = 0;
        for (int i = tid; i < NA; i += 256) {
            if (vals[i] > best) { best = vals[i]; bi = i; }
        }
        sv[tid] = best;
        si[tid] = bi;
        __syncthreads();
        for (int off = 128; off > 0; off >>= 1) {
            if (tid < off) {
                if (sv[tid + off] > sv[tid]) { sv[tid] = sv[tid + off]; si[tid] = si[tid + off]; }
            }
            __syncthreads();
        }
        if (tid == 0) { top[it] = sv[0]; vals[si[0]] = -1.f; }
        __syncthreads();
    }
    if (tid == 0) {
        float o = ff2b[0];
        for (int j = 0; j < 10; j++) {
            float h = ff1b[j];
            for (int i = 0; i < 10; i++) h += top[i] * ff1w[i * 10 + j];
            h = fmaxf(h, 0.f);
            o += h * ff2w[j];
        }
        out[b] = o;
    }
}

// ---------------- launcher ----------------
extern "C" void kernel_launch(void* const* d_in, const int* in_sizes, int n_in,
                              void* d_out, int out_size) {
    const int* art_w   = (const int*)d_in[0];
    const int* tpl_w   = (const int*)d_in[2];
    const float* am    = (const float*)d_in[4];
    const float* tm    = (const float*)d_in[5];
    const float* emb   = (const float*)d_in[6];
    const float* exp_w = (const float*)d_in[7];
    const float* exp_b = (const float*)d_in[8];
    const float* ref_w = (const float*)d_in[9];
    const float* ref_b = (const float*)d_in[10];
    const float* ff1w  = (const float*)d_in[11];
    const float* ff1b  = (const float*)d_in[12];
    const float* ff2w  = (const float*)d_in[13];
    const float* ff2b  = (const float*)d_in[14];

    float *artf, *tplf, *a2p, *t2p, *rmp;
    __nv_bfloat16 *arth, *artm, *tplh, *tplm, *wth, *wtm;
    cudaGetSymbolAddress((void**)&artf, g_art);
    cudaGetSymbolAddress((void**)&tplf, g_tpl);
    cudaGetSymbolAddress((void**)&arth, g_art_h);
    cudaGetSymbolAddress((void**)&artm, g_art_m);
    cudaGetSymbolAddress((void**)&tplh, g_tpl_h);
    cudaGetSymbolAddress((void**)&tplm, g_tpl_m);
    cudaGetSymbolAddress((void**)&wth, g_wth);
    cudaGetSymbolAddress((void**)&wtm, g_wtm);
    cudaGetSymbolAddress((void**)&a2p, g_a2);
    cudaGetSymbolAddress((void**)&t2p, g_t2);
    cudaGetSymbolAddress((void**)&rmp, g_rowmax);

    const size_t ASZ = (size_t)NB * NA * ND;
    const size_t TSZ = (size_t)NB * NT * ND;
    float* af[2] = {artf, artf + ASZ};
    float* tf[2] = {tplf, tplf + TSZ};
    __nv_bfloat16* ah[2] = {arth, arth + ASZ};
    __nv_bfloat16* amid[2] = {artm, artm + ASZ};
    __nv_bfloat16* th[2] = {tplh, tplh + TSZ};
    __nv_bfloat16* tmid[2] = {tplm, tplm + TSZ};

    cudaFuncSetAttribute(resblock_mma, cudaFuncAttributeMaxDynamicSharedMemorySize, RB_SMEM);

    wconv_kernel<<<dim3(30, 8, 16), dim3(32, 32)>>>(exp_w, ref_w, wth, wtm);
    gather_kernel<<<(NB * NA * 64 + 255) / 256, 256>>>(art_w, emb, af[0], ah[0], amid[0], NB * NA);
    gather_kernel<<<(NB * NT * 64 + 255) / 256, 256>>>(tpl_w, emb, tf[0], th[0], tmid[0], NB * NT);

    const int dils[10] = {1, 2, 4, 8, 16, 32, 32, 1, 1, 1};
    int cur = 0;
    for (int i = 0; i < 10; i++) {
        const __nv_bfloat16* wh = wth + (size_t)i * 3 * TWO_D * ND;
        const __nv_bfloat16* wm = wtm + (size_t)i * 3 * TWO_D * ND;
        const float* bias = (i < 7) ? exp_b + (size_t)i * TWO_D
                                    : ref_b + (size_t)(i - 7) * TWO_D;
        resblock_mma<<<dim3(128 + 64, 4), 256, RB_SMEM>>>(
            af[cur], ah[cur], amid[cur], af[1 - cur], ah[1 - cur], amid[1 - cur],
            tf[cur], th[cur], tmid[cur], tf[1 - cur], th[1 - cur], tmid[1 - cur],
            wh, wm, bias, dils[i]);
        cur ^= 1;
    }
    // 10 flips -> final tensors back in buffer 0

    norm_kernel<<<NB * NA, 64>>>(af[cur], a2p);
    norm_kernel<<<NB * NT, 64>>>(tf[cur], t2p);

    dist_kernel<<<dim3(NA / DA, NB), 256>>>(af[cur], tf[cur], a2p, t2p, am, tm, rmp);

    topk_mlp_kernel<<<NB, 256>>>(rmp, ff1w, ff1b, ff2w, ff2b, (float*)d_out);
}

// round 6
// speedup vs baseline: 2.8134x; 1.0520x over previous
#include <cuda_runtime.h>
#include <cuda_bf16.h>
#include <math.h>
#include <stdint.h>

// Problem constants
#define NB 16
#define NA 1024
#define NT 512
#define ND 256
#define TWO_D 512

// ---------------- scratch (no allocations allowed) ----------------
__device__ float g_art[2][NB * NA * ND];
__device__ float g_tpl[2][NB * NT * ND];
__device__ __nv_bfloat16 g_art_h[2][NB * NA * ND];
__device__ __nv_bfloat16 g_art_m[2][NB * NA * ND];
__device__ __nv_bfloat16 g_tpl_h[2][NB * NT * ND];
__device__ __nv_bfloat16 g_tpl_m[2][NB * NT * ND];
__device__ __nv_bfloat16 g_wth[10 * 3 * TWO_D * ND];
__device__ __nv_bfloat16 g_wtm[10 * 3 * TWO_D * ND];
__device__ float g_a2[NB * NA];
__device__ float g_t2[NB * NT];
__device__ float g_rowmax[NB * NA];

// ---------------- helpers ----------------
__device__ __forceinline__ uint32_t smem_u32(const void* p) {
    uint32_t a;
    asm("{ .reg .u64 t; cvta.to.shared.u64 t, %1; cvt.u32.u64 %0, t; }" : "=r"(a) : "l"(p));
    return a;
}
__device__ __forceinline__ void bsplit(float x, __nv_bfloat16& h, __nv_bfloat16& m) {
    h = __float2bfloat16(x);
    m = __float2bfloat16(x - __bfloat162float(h));
}
__device__ __forceinline__ void ldsm4(uint32_t a, uint32_t* r) {
    asm volatile("ldmatrix.sync.aligned.m8n8.x4.shared.b16 {%0,%1,%2,%3}, [%4];"
                 : "=r"(r[0]), "=r"(r[1]), "=r"(r[2]), "=r"(r[3]) : "r"(a));
}
__device__ __forceinline__ void mma16816(float* c, const uint32_t* a, uint32_t b0, uint32_t b1) {
    asm volatile(
        "mma.sync.aligned.m16n8k16.row.col.f32.bf16.bf16.f32 "
        "{%0,%1,%2,%3}, {%4,%5,%6,%7}, {%8,%9}, {%0,%1,%2,%3};"
        : "+f"(c[0]), "+f"(c[1]), "+f"(c[2]), "+f"(c[3])
        : "r"(a[0]), "r"(a[1]), "r"(a[2]), "r"(a[3]), "r"(b0), "r"(b1));
}
__device__ __forceinline__ void cpasync16(uint32_t dst, const void* src, uint32_t sz) {
    asm volatile("cp.async.cg.shared.global [%0], [%1], 16, %2;"
                 :: "r"(dst), "l"(src), "r"(sz));
}

// ---------------- embedding gather (f32 + hi/mid bf16) ----------------
__global__ void gather_kernel(const int* __restrict__ words,
                              const float* __restrict__ emb,
                              float* __restrict__ outf,
                              __nv_bfloat16* __restrict__ outh,
                              __nv_bfloat16* __restrict__ outm, int nrows) {
    int idx = blockIdx.x * blockDim.x + threadIdx.x;
    int total = nrows * (ND / 4);
    if (idx >= total) return;
    int row = idx >> 6;
    int d4  = idx & 63;
    int w = words[row];
    float4 v = reinterpret_cast<const float4*>(emb)[(size_t)w * 64 + d4];
    size_t o = (size_t)row * ND + d4 * 4;
    *reinterpret_cast<float4*>(outf + o) = v;
    __nv_bfloat16 h0, h1, h2, h3, m0, m1, m2, m3;
    bsplit(v.x, h0, m0); bsplit(v.y, h1, m1); bsplit(v.z, h2, m2); bsplit(v.w, h3, m3);
    *reinterpret_cast<__nv_bfloat162*>(outh + o)     = __halves2bfloat162(h0, h1);
    *reinterpret_cast<__nv_bfloat162*>(outh + o + 2) = __halves2bfloat162(h2, h3);
    *reinterpret_cast<__nv_bfloat162*>(outm + o)     = __halves2bfloat162(m0, m1);
    *reinterpret_cast<__nv_bfloat162*>(outm + o + 2) = __halves2bfloat162(m2, m3);
}

// ---------------- weight transpose + split: W[k][d][c] -> Wt[lk][c][d] hi/mid ----------------
__global__ void wconv_kernel(const float* __restrict__ exp_w, const float* __restrict__ ref_w,
                             __nv_bfloat16* __restrict__ wh, __nv_bfloat16* __restrict__ wm) {
    __shared__ float t[32][33];
    int lk = blockIdx.x;
    int d0 = blockIdx.y * 32;
    int c0 = blockIdx.z * 32;
    const float* src = (lk < 21) ? exp_w + (size_t)lk * (ND * TWO_D)
                                 : ref_w + (size_t)(lk - 21) * (ND * TWO_D);
    t[threadIdx.y][threadIdx.x] = src[(size_t)(d0 + threadIdx.y) * TWO_D + c0 + threadIdx.x];
    __syncthreads();
    float v = t[threadIdx.x][threadIdx.y];
    size_t o = ((size_t)lk * TWO_D + c0 + threadIdx.y) * ND + d0 + threadIdx.x;
    __nv_bfloat16 h, m;
    bsplit(v, h, m);
    wh[o] = h;
    wm[o] = m;
}

// ---------------- mma.sync res-block v4 ----------------
// CTA 128 rows x 64 GLU pairs, B rows interleaved (even=a, odd=g) -> register GLU.
// 8 warps = 2M(64) x 4N(32). K-stage 32, 24 stages, 3-ring, 1 sync/stage.
// mma issue order: dependency distance 4 across the 4 accumulators of each M-group.
#define RB_STAGE 32768  // Ah 8K | Am 8K | Bh 8K | Bm 8K
#define RB_SMEM  98304  // 3 stages

__global__ __launch_bounds__(256, 2)
void resblock_mma(const float* __restrict__ ArtF,
                  const __nv_bfloat16* __restrict__ ArtH, const __nv_bfloat16* __restrict__ ArtM,
                  float* __restrict__ ArtOF, __nv_bfloat16* __restrict__ ArtOH,
                  __nv_bfloat16* __restrict__ ArtOM,
                  const float* __restrict__ TplF,
                  const __nv_bfloat16* __restrict__ TplH, const __nv_bfloat16* __restrict__ TplM,
                  float* __restrict__ TplOF, __nv_bfloat16* __restrict__ TplOH,
                  __nv_bfloat16* __restrict__ TplOM,
                  const __nv_bfloat16* __restrict__ Wth, const __nv_bfloat16* __restrict__ Wtm,
                  const float* __restrict__ bias, int dil) {
    extern __shared__ char smem[];
    const uint32_t sb = smem_u32(smem);
    const int tid = threadIdx.x;
    const int lane = tid & 31;
    const int wid = tid >> 5;

    const bool isA = blockIdx.x < 128;
    const int mb = isA ? blockIdx.x : (blockIdx.x - 128);
    const int L = isA ? NA : NT;
    const __nv_bfloat16* Xh = isA ? ArtH : TplH;
    const __nv_bfloat16* Xm = isA ? ArtM : TplM;
    const float* Xf = isA ? ArtF : TplF;
    float* Yf = isA ? ArtOF : TplOF;
    __nv_bfloat16* Yh = isA ? ArtOH : TplOH;
    __nv_bfloat16* Ym = isA ? ArtOM : TplOM;

    const int rowBase = mb * 128;
    const int pairBase = blockIdx.y * 64;
    const int bb = rowBase / L;
    const int lBase = rowBase - bb * L;

    const int warpM = (wid & 1) * 64;
    const int warpN = (wid >> 1) * 32;

    uint32_t offA[4];
    int swzA[4];
    {
        int r15 = lane & 15;
#pragma unroll
        for (int mt = 0; mt < 4; mt++) {
            int r = warpM + mt * 16 + r15;
            offA[mt] = r * 64;
            swzA[mt] = (r >> 1) & 3;
        }
    }
    const int cbA = lane >> 4;
    uint32_t offB[2];
    int swzB[2];
    const int jm = lane >> 3;
    const int cbB = jm & 1;
    {
        int rb = (jm >> 1) * 8 + (lane & 7);
#pragma unroll
        for (int nt = 0; nt < 2; nt++) {
            int r = warpN + nt * 16 + rb;
            offB[nt] = r * 64;
            swzB[nt] = (r >> 1) & 3;
        }
    }

    float acc[4][4][4];
#pragma unroll
    for (int i = 0; i < 4; i++)
#pragma unroll
        for (int j = 0; j < 4; j++)
#pragma unroll
            for (int q = 0; q < 4; q++) acc[i][j][q] = 0.f;

    auto issue = [&](int s) {
        if (s < 24) {
            const int buf = s - (s / 3) * 3;
            const uint32_t base = sb + buf * RB_STAGE;
            const int tap = s >> 3;
            const int k0 = (s & 7) << 5;
            const int shift = (tap - 1) * dil;
#pragma unroll
            for (int q = 0; q < 2; q++) {
                int idx = tid + q * 256;
                int row = idx >> 2;
                int kc = idx & 3;
                int kcs = kc ^ ((row >> 1) & 3);
                uint32_t dst = base + row * 64 + kcs * 16;
                int p = lBase + row + shift;
                uint32_t sz = (p >= 0 && p < L) ? 16u : 0u;
                int pc = p < 0 ? 0 : (p >= L ? L - 1 : p);
                size_t aoff = (size_t)(bb * L + pc) * ND + k0 + kc * 8;
                cpasync16(dst, Xh + aoff, sz);
                cpasync16(dst + 8192, Xm + aoff, sz);
                int pr = pairBase + (row >> 1);
                int chan = (row & 1) ? (256 + pr) : pr;
                size_t boff = ((size_t)tap * TWO_D + chan) * ND + k0 + kc * 8;
                cpasync16(dst + 16384, Wth + boff, 16u);
                cpasync16(dst + 24576, Wtm + boff, 16u);
            }
        }
        asm volatile("cp.async.commit_group;");
    };

    auto domma = [&](int buf) {
        const uint32_t base = sb + buf * RB_STAGE;
        uint32_t bh[2][4], bm[2][4];
        uint32_t ah[2][4], am[2][4];
#pragma unroll
        for (int h = 0; h < 2; h++) {
#pragma unroll
            for (int nt = 0; nt < 2; nt++) {
                uint32_t a = base + offB[nt] + (uint32_t)(((cbB + 2 * h) ^ swzB[nt]) * 16);
                ldsm4(a + 16384, bh[nt]);
                ldsm4(a + 24576, bm[nt]);
            }
            {
                uint32_t a = base + offA[0] + (uint32_t)(((cbA + 2 * h) ^ swzA[0]) * 16);
                ldsm4(a, ah[0]);
                ldsm4(a + 8192, am[0]);
            }
            int cur = 0;
#pragma unroll
            for (int mt = 0; mt < 4; mt++) {
                int nxt = cur ^ 1;
                if (mt < 3) {
                    uint32_t a = base + offA[mt + 1] +
                                 (uint32_t)(((cbA + 2 * h) ^ swzA[mt + 1]) * 16);
                    ldsm4(a, ah[nxt]);
                    ldsm4(a + 8192, am[nxt]);
                }
                // interleaved: dependency distance 4 across accumulators
                mma16816(acc[mt][0], ah[cur], bh[0][0], bh[0][1]);
                mma16816(acc[mt][1], ah[cur], bh[0][2], bh[0][3]);
                mma16816(acc[mt][2], ah[cur], bh[1][0], bh[1][1]);
                mma16816(acc[mt][3], ah[cur], bh[1][2], bh[1][3]);
                mma16816(acc[mt][0], ah[cur], bm[0][0], bm[0][1]);
                mma16816(acc[mt][1], ah[cur], bm[0][2], bm[0][3]);
                mma16816(acc[mt][2], ah[cur], bm[1][0], bm[1][1]);
                mma16816(acc[mt][3], ah[cur], bm[1][2], bm[1][3]);
                mma16816(acc[mt][0], am[cur], bh[0][0], bh[0][1]);
                mma16816(acc[mt][1], am[cur], bh[0][2], bh[0][3]);
                mma16816(acc[mt][2], am[cur], bh[1][0], bh[1][1]);
                mma16816(acc[mt][3], am[cur], bh[1][2], bh[1][3]);
                cur = nxt;
            }
        }
    };

    issue(0);
    issue(1);
    int buf = 0;
    for (int s = 0; s < 24; s++) {
        asm volatile("cp.async.wait_group 1;");
        __syncthreads();
        issue(s + 2);
        domma(buf);
        buf = (buf == 2) ? 0 : buf + 1;
    }

    // ---- in-register epilogue: bias + GLU + residual + bf16 split ----
    {
        const int laneRow = lane >> 2;
        const int laneP = lane & 3;
        const int pB = pairBase + (warpN >> 1) + laneP;
#pragma unroll
        for (int nj = 0; nj < 4; nj++) {
            const int p = pB + nj * 4;
            const float ba = bias[p];
            const float bg = bias[256 + p];
#pragma unroll
            for (int mt = 0; mt < 4; mt++) {
                const int r0 = rowBase + warpM + mt * 16 + laneRow;
                const float* c = acc[mt][nj];
#pragma unroll
                for (int hrow = 0; hrow < 2; hrow++) {
                    const size_t o = (size_t)(r0 + 8 * hrow) * ND + p;
                    float a = c[2 * hrow] + ba;
                    float g = c[2 * hrow + 1] + bg;
                    float y = Xf[o] + a * (1.f / (1.f + expf(-g)));
                    Yf[o] = y;
                    __nv_bfloat16 hh, mm;
                    bsplit(y, hh, mm);
                    Yh[o] = hh;
                    Ym[o] = mm;
                }
            }
        }
    }
}

// ---------------- squared norms per row ----------------
__global__ void norm_kernel(const float* __restrict__ X, float* __restrict__ out) {
    int row = blockIdx.x;
    int tid = threadIdx.x;
    float4 v = reinterpret_cast<const float4*>(X + (size_t)row * ND)[tid];
    float s = v.x * v.x + v.y * v.y + v.z * v.z + v.w * v.w;
#pragma unroll
    for (int off = 16; off > 0; off >>= 1)
        s += __shfl_down_sync(0xFFFFFFFFu, s, off);
    __shared__ float ws[2];
    if ((tid & 31) == 0) ws[tid >> 5] = s;
    __syncthreads();
    if (tid == 0) out[row] = ws[0] + ws[1];
}

// ---------------- tensorized distance + row-max ----------------
// CTA: 128 art rows x 128 tpl cols per chunk; blockIdx.z picks 2 of 4 T-chunks.
// dot via 3-split bf16 mma; epilogue: exp(-dist)*masks, reg row-max -> smem -> global atomicMax.
#define DI_STAGE 32768  // Ah 8K | Am 8K | Th 8K | Tm 8K
#define DI_SMEM  98304

__global__ __launch_bounds__(256)
void dist_mma(const __nv_bfloat16* __restrict__ Ah_, const __nv_bfloat16* __restrict__ Am_,
              const __nv_bfloat16* __restrict__ Th_, const __nv_bfloat16* __restrict__ Tm_,
              const float* __restrict__ a2, const float* __restrict__ t2,
              const float* __restrict__ amask, const float* __restrict__ tmask,
              float* __restrict__ rowmax_out) {
    extern __shared__ char smem[];
    __shared__ int rmax[128];
    __shared__ float st2[128], stm[128];
    const uint32_t sb = smem_u32(smem);
    const int tid = threadIdx.x;
    const int lane = tid & 31;
    const int wid = tid >> 5;

    const int b = blockIdx.y;
    const int rowBase = blockIdx.x * 128;   // within batch

    if (tid < 128) rmax[tid] = 0;

    const int warpM = (wid & 1) * 64;
    const int warpN = (wid >> 1) * 32;

    uint32_t offA[4];
    int swzA[4];
    {
        int r15 = lane & 15;
#pragma unroll
        for (int mt = 0; mt < 4; mt++) {
            int r = warpM + mt * 16 + r15;
            offA[mt] = r * 64;
            swzA[mt] = (r >> 1) & 3;
        }
    }
    const int cbA = lane >> 4;
    uint32_t offB[2];
    int swzB[2];
    const int jm = lane >> 3;
    const int cbB = jm & 1;
    {
        int rb = (jm >> 1) * 8 + (lane & 7);
#pragma unroll
        for (int nt = 0; nt < 2; nt++) {
            int r = warpN + nt * 16 + rb;
            offB[nt] = r * 64;
            swzB[nt] = (r >> 1) & 3;
        }
    }

    // per-thread row constants
    float a2v[4][2], amv[4][2];
    float tmax[4][2];
#pragma unroll
    for (int mt = 0; mt < 4; mt++)
#pragma unroll
        for (int h = 0; h < 2; h++) {
            int r = rowBase + warpM + mt * 16 + (lane >> 2) + 8 * h;
            a2v[mt][h] = a2[b * NA + r];
            amv[mt][h] = amask[b * NA + r];
            tmax[mt][h] = 0.f;
        }

    for (int tc = 0; tc < 2; tc++) {
        const int tBase = (blockIdx.z * 2 + tc) * 128;

        if (tid < 128) {
            st2[tid] = t2[b * NT + tBase + tid];
            stm[tid] = tmask[b * NT + tBase + tid];
        }

        float acc[4][4][4];
#pragma unroll
        for (int i = 0; i < 4; i++)
#pragma unroll
            for (int j = 0; j < 4; j++)
#pragma unroll
                for (int q = 0; q < 4; q++) acc[i][j][q] = 0.f;

        auto issue = [&](int s) {
            if (s < 8) {
                const int buf = s - (s / 3) * 3;
                const uint32_t base = sb + buf * DI_STAGE;
                const int k0 = s << 5;
#pragma unroll
                for (int q = 0; q < 2; q++) {
                    int idx = tid + q * 256;
                    int row = idx >> 2;
                    int kc = idx & 3;
                    int kcs = kc ^ ((row >> 1) & 3);
                    uint32_t dst = base + row * 64 + kcs * 16;
                    size_t aoff = (size_t)(b * NA + rowBase + row) * ND + k0 + kc * 8;
                    cpasync16(dst, Ah_ + aoff, 16u);
                    cpasync16(dst + 8192, Am_ + aoff, 16u);
                    size_t toff = (size_t)(b * NT + tBase + row) * ND + k0 + kc * 8;
                    cpasync16(dst + 16384, Th_ + toff, 16u);
                    cpasync16(dst + 24576, Tm_ + toff, 16u);
                }
            }
            asm volatile("cp.async.commit_group;");
        };

        auto domma = [&](int buf) {
            const uint32_t base = sb + buf * DI_STAGE;
            uint32_t bh[2][4], bm[2][4];
            uint32_t ah[2][4], am[2][4];
#pragma unroll
            for (int h = 0; h < 2; h++) {
#pragma unroll
                for (int nt = 0; nt < 2; nt++) {
                    uint32_t a = base + offB[nt] + (uint32_t)(((cbB + 2 * h) ^ swzB[nt]) * 16);
                    ldsm4(a + 16384, bh[nt]);
                    ldsm4(a + 24576, bm[nt]);
                }
                {
                    uint32_t a = base + offA[0] + (uint32_t)(((cbA + 2 * h) ^ swzA[0]) * 16);
                    ldsm4(a, ah[0]);
                    ldsm4(a + 8192, am[0]);
                }
                int cur = 0;
#pragma unroll
                for (int mt = 0; mt < 4; mt++) {
                    int nxt = cur ^ 1;
                    if (mt < 3) {
                        uint32_t a = base + offA[mt + 1] +
                                     (uint32_t)(((cbA + 2 * h) ^ swzA[mt + 1]) * 16);
                        ldsm4(a, ah[nxt]);
                        ldsm4(a + 8192, am[nxt]);
                    }
                    mma16816(acc[mt][0], ah[cur], bh[0][0], bh[0][1]);
                    mma16816(acc[mt][1], ah[cur], bh[0][2], bh[0][3]);
                    mma16816(acc[mt][2], ah[cur], bh[1][0], bh[1][1]);
                    mma16816(acc[mt][3], ah[cur], bh[1][2], bh[1][3]);
                    mma16816(acc[mt][0], ah[cur], bm[0][0], bm[0][1]);
                    mma16816(acc[mt][1], ah[cur], bm[0][2], bm[0][3]);
                    mma16816(acc[mt][2], ah[cur], bm[1][0], bm[1][1]);
                    mma16816(acc[mt][3], ah[cur], bm[1][2], bm[1][3]);
                    mma16816(acc[mt][0], am[cur], bh[0][0], bh[0][1]);
                    mma16816(acc[mt][1], am[cur], bh[0][2], bh[0][3]);
                    mma16816(acc[mt][2], am[cur], bh[1][0], bh[1][1]);
                    mma16816(acc[mt][3], am[cur], bh[1][2], bh[1][3]);
                    cur = nxt;
                }
            }
        };

        issue(0);
        issue(1);
        int buf = 0;
        for (int s = 0; s < 8; s++) {
            asm volatile("cp.async.wait_group 1;");
            __syncthreads();
            issue(s + 2);
            domma(buf);
            buf = (buf == 2) ? 0 : buf + 1;
        }

        // epilogue for this T chunk
        const int colL = warpN + 2 * (lane & 3);
#pragma unroll
        for (int mt = 0; mt < 4; mt++)
#pragma unroll
            for (int h = 0; h < 2; h++) {
                float best = tmax[mt][h];
                const float a2r = a2v[mt][h];
                const float amr = amv[mt][h];
#pragma unroll
                for (int nj = 0; nj < 4; nj++) {
#pragma unroll
                    for (int cc = 0; cc < 2; cc++) {
                        int cl = colL + nj * 8 + cc;
                        float d = a2r + st2[cl] - 2.f * acc[mt][nj][2 * h + cc];
                        d = fmaxf(d, 0.f);
                        best = fmaxf(best, expf(-d) * stm[cl] * amr);
                    }
                }
                tmax[mt][h] = best;
            }
        __syncthreads();   // guard smem reuse by next chunk
    }

    // reduce across quad lanes (same row, different cols)
#pragma unroll
    for (int mt = 0; mt < 4; mt++)
#pragma unroll
        for (int h = 0; h < 2; h++) {
            float v = tmax[mt][h];
            v = fmaxf(v, __shfl_xor_sync(0xFFFFFFFFu, v, 1));
            v = fmaxf(v, __shfl_xor_sync(0xFFFFFFFFu, v, 2));
            if ((lane & 3) == 0)
                atomicMax(&rmax[warpM + mt * 16 + (lane >> 2) + 8 * h], __float_as_int(v));
        }
    __syncthreads();
    if (tid < 128)
        atomicMax(reinterpret_cast<int*>(rowmax_out) + b * NA + rowBase + tid, rmax[tid]);
}

// ---------------- top-10 + MLP ----------------
__global__ void topk_mlp_kernel(const float* __restrict__ rowmax,
                                const float* __restrict__ ff1w,
                                const float* __restrict__ ff1b,
                                const float* __restrict__ ff2w,
                                const float* __restrict__ ff2b,
                                float* __restrict__ out) {
    int b = blockIdx.x;
    __shared__ float vals[NA];
    __shared__ float sv[256];
    __shared__ int si[256];
    __shared__ float top[10];
    int tid = threadIdx.x;
#pragma unroll
    for (int q = 0; q < 4; q++) vals[tid + q * 256] = rowmax[b * NA + tid + q * 256];
    __syncthreads();
    for (int it = 0; it < 10; it++) {
        float best = -1.f;
        int bi = 0;
        for (int i = tid; i < NA; i += 256) {
            if (vals[i] > best) { best = vals[i]; bi = i; }
        }
        sv[tid] = best;
        si[tid] = bi;
        __syncthreads();
        for (int off = 128; off > 0; off >>= 1) {
            if (tid < off) {
                if (sv[tid + off] > sv[tid]) { sv[tid] = sv[tid + off]; si[tid] = si[tid + off]; }
            }
            __syncthreads();
        }
        if (tid == 0) { top[it] = sv[0]; vals[si[0]] = -1.f; }
        __syncthreads();
    }
    if (tid == 0) {
        float o = ff2b[0];
        for (int j = 0; j < 10; j++) {
            float h = ff1b[j];
            for (int i = 0; i < 10; i++) h += top[i] * ff1w[i * 10 + j];
            h = fmaxf(h, 0.f);
            o += h * ff2w[j];
        }
        out[b] = o;
    }
}

// ---------------- launcher ----------------
extern "C" void kernel_launch(void* const* d_in, const int* in_sizes, int n_in,
                              void* d_out, int out_size) {
    const int* art_w   = (const int*)d_in[0];
    const int* tpl_w   = (const int*)d_in[2];
    const float* am    = (const float*)d_in[4];
    const float* tm    = (const float*)d_in[5];
    const float* emb   = (const float*)d_in[6];
    const float* exp_w = (const float*)d_in[7];
    const float* exp_b = (const float*)d_in[8];
    const float* ref_w = (const float*)d_in[9];
    const float* ref_b = (const float*)d_in[10];
    const float* ff1w  = (const float*)d_in[11];
    const float* ff1b  = (const float*)d_in[12];
    const float* ff2w  = (const float*)d_in[13];
    const float* ff2b  = (const float*)d_in[14];

    float *artf, *tplf, *a2p, *t2p, *rmp;
    __nv_bfloat16 *arth, *artm, *tplh, *tplm, *wth, *wtm;
    cudaGetSymbolAddress((void**)&artf, g_art);
    cudaGetSymbolAddress((void**)&tplf, g_tpl);
    cudaGetSymbolAddress((void**)&arth, g_art_h);
    cudaGetSymbolAddress((void**)&artm, g_art_m);
    cudaGetSymbolAddress((void**)&tplh, g_tpl_h);
    cudaGetSymbolAddress((void**)&tplm, g_tpl_m);
    cudaGetSymbolAddress((void**)&wth, g_wth);
    cudaGetSymbolAddress((void**)&wtm, g_wtm);
    cudaGetSymbolAddress((void**)&a2p, g_a2);
    cudaGetSymbolAddress((void**)&t2p, g_t2);
    cudaGetSymbolAddress((void**)&rmp, g_rowmax);

    const size_t ASZ = (size_t)NB * NA * ND;
    const size_t TSZ = (size_t)NB * NT * ND;
    float* af[2] = {artf, artf + ASZ};
    float* tf[2] = {tplf, tplf + TSZ};
    __nv_bfloat16* ah[2] = {arth, arth + ASZ};
    __nv_bfloat16* amid[2] = {artm, artm + ASZ};
    __nv_bfloat16* th[2] = {tplh, tplh + TSZ};
    __nv_bfloat16* tmid[2] = {tplm, tplm + TSZ};

    cudaFuncSetAttribute(resblock_mma, cudaFuncAttributeMaxDynamicSharedMemorySize, RB_SMEM);
    cudaFuncSetAttribute(dist_mma, cudaFuncAttributeMaxDynamicSharedMemorySize, DI_SMEM);

    wconv_kernel<<<dim3(30, 8, 16), dim3(32, 32)>>>(exp_w, ref_w, wth, wtm);
    gather_kernel<<<(NB * NA * 64 + 255) / 256, 256>>>(art_w, emb, af[0], ah[0], amid[0], NB * NA);
    gather_kernel<<<(NB * NT * 64 + 255) / 256, 256>>>(tpl_w, emb, tf[0], th[0], tmid[0], NB * NT);

    const int dils[10] = {1, 2, 4, 8, 16, 32, 32, 1, 1, 1};
    int cur = 0;
    for (int i = 0; i < 10; i++) {
        const __nv_bfloat16* wh = wth + (size_t)i * 3 * TWO_D * ND;
        const __nv_bfloat16* wm = wtm + (size_t)i * 3 * TWO_D * ND;
        const float* bias = (i < 7) ? exp_b + (size_t)i * TWO_D
                                    : ref_b + (size_t)(i - 7) * TWO_D;
        resblock_mma<<<dim3(128 + 64, 4), 256, RB_SMEM>>>(
            af[cur], ah[cur], amid[cur], af[1 - cur], ah[1 - cur], amid[1 - cur],
            tf[cur], th[cur], tmid[cur], tf[1 - cur], th[1 - cur], tmid[1 - cur],
            wh, wm, bias, dils[i]);
        cur ^= 1;
    }
    // 10 flips -> final tensors back in buffer 0

    norm_kernel<<<NB * NA, 64>>>(af[cur], a2p);
    norm_kernel<<<NB * NT, 64>>>(tf[cur], t2p);

    cudaMemsetAsync(rmp, 0, NB * NA * sizeof(float));
    dist_mma<<<dim3(NA / 128, NB, 2), 256, DI_SMEM>>>(
        ah[cur], amid[cur], th[cur], tmid[cur], a2p, t2p, am, tm, rmp);

    topk_mlp_kernel<<<NB, 256>>>(rmp, ff1w, ff1b, ff2w, ff2b, (float*)d_out);
}